// round 12
// baseline (speedup 1.0000x reference)
#include <cuda_runtime.h>
#include <cuda_fp16.h>
#include <math.h>
#include <stdint.h>

#define BB 2
#define SS 2048
#define DD 1024
#define HH 16
#define DHD 64
#define DFF 4096
#define NROWS (BB * SS)
#define NQKV 3072

// ---------------- scratch (device globals; no allocation) ----------------
__device__ __half g_ln[NROWS * DD];
__device__ __half g_qkv[NROWS * NQKV];
__device__ __half g_attn[NROWS * DD];
__device__ float  g_h1[NROWS * DD];
__device__ __half g_f1[NROWS * DFF];
__device__ __half g_wqkv[DD * NQKV];
__device__ float  g_bqkv[NQKV];
__device__ __half g_wo[DD * DD];
__device__ __half g_w1[DD * DFF];
__device__ __half g_w2[DFF * DD];

// ---------------- helpers --------------------------------------------------
__device__ __forceinline__ uint32_t smem_u32(const void* p) {
    uint32_t a;
    asm("{ .reg .u64 t; cvta.to.shared.u64 t, %1; cvt.u32.u64 %0, t; }" : "=r"(a) : "l"(p));
    return a;
}
__device__ __forceinline__ void cp16(void* dst_smem, const void* src) {
    uint32_t d;
    asm("{ .reg .u64 t; cvta.to.shared.u64 t, %1; cvt.u32.u64 %0, t; }"
        : "=r"(d) : "l"(dst_smem));
    asm volatile("cp.async.cg.shared.global [%0], [%1], 16;" :: "r"(d), "l"(src));
}
__device__ __forceinline__ void cp_commit() {
    asm volatile("cp.async.commit_group;");
}
template <int N>
__device__ __forceinline__ void cp_wait() {
    asm volatile("cp.async.wait_group %0;" :: "n"(N));
}
__device__ __forceinline__ void ldm_x4(uint32_t r[4], uint32_t addr) {
    asm volatile("ldmatrix.sync.aligned.m8n8.x4.shared.b16 {%0,%1,%2,%3}, [%4];"
        : "=r"(r[0]), "=r"(r[1]), "=r"(r[2]), "=r"(r[3]) : "r"(addr));
}
__device__ __forceinline__ void ldm_x4t(uint32_t r[4], uint32_t addr) {
    asm volatile("ldmatrix.sync.aligned.m8n8.x4.trans.shared.b16 {%0,%1,%2,%3}, [%4];"
        : "=r"(r[0]), "=r"(r[1]), "=r"(r[2]), "=r"(r[3]) : "r"(addr));
}
__device__ __forceinline__ void mma16(float c[4], const uint32_t a[4], const uint32_t b[2]) {
    asm volatile(
        "mma.sync.aligned.m16n8k16.row.col.f32.f16.f16.f32 "
        "{%0,%1,%2,%3}, {%4,%5,%6,%7}, {%8,%9}, {%0,%1,%2,%3};"
        : "+f"(c[0]), "+f"(c[1]), "+f"(c[2]), "+f"(c[3])
        : "r"(a[0]), "r"(a[1]), "r"(a[2]), "r"(a[3]), "r"(b[0]), "r"(b[1]));
}
__device__ __forceinline__ uint32_t packh2(float lo, float hi) {
    __half2 h = __floats2half2_rn(lo, hi);
    return *(uint32_t*)&h;
}
__device__ __forceinline__ float ex2f(float x) {
    float r;
    asm("ex2.approx.f32 %0, %1;" : "=f"(r) : "f"(x));
    return r;
}
__device__ __forceinline__ float gelu_tanh_f(float h) {
    const float c = 0.7978845608028654f;
    float u = c * (h + 0.044715f * h * h * h);
    return 0.5f * h * (1.0f + tanhf(u));
}

// ---------------- ONE fused pack kernel, 8 float4 in flight per thread -----
#define NW (DD * DD / 4)
#define NF (DD * DFF / 4)
#define PACK_TOT (4L * NW + 2L * NF + 768)
#define PACK_BLOCKS ((PACK_TOT + 2047) / 2048)
__global__ void __launch_bounds__(256) pack_all(
    const float* __restrict__ wq, const float* __restrict__ wk,
    const float* __restrict__ wv, const float* __restrict__ wo,
    const float* __restrict__ w1, const float* __restrict__ w2,
    const float* __restrict__ bq, const float* __restrict__ bk,
    const float* __restrict__ bv,
    __half* __restrict__ wqkv, __half* __restrict__ woh,
    __half* __restrict__ w1h, __half* __restrict__ w2h,
    float* __restrict__ bqkv)
{
    #pragma unroll
    for (int j = 0; j < 8; j++) {
        long i = (long)blockIdx.x * 2048 + j * 256 + threadIdx.x;
        if (i >= PACK_TOT) break;
        if (i < 3L * NW) {
            const float* src = (i < NW) ? wq : (i < 2L * NW) ? wk : wv;
            int coff = (i < NW) ? 0 : (i < 2L * NW) ? DD : 2 * DD;
            long ii = i % NW;
            int row = (int)(ii >> 8), c4 = ((int)ii & 255) << 2;
            float4 v = ((const float4*)src)[ii];
            __half2* o = (__half2*)(wqkv + (size_t)row * NQKV + coff + c4);
            o[0] = __floats2half2_rn(v.x, v.y);
            o[1] = __floats2half2_rn(v.z, v.w);
        } else if (i < 4L * NW) {
            long ii = i - 3L * NW;
            float4 v = ((const float4*)wo)[ii];
            __half2* o = (__half2*)(woh + ii * 4);
            o[0] = __floats2half2_rn(v.x, v.y);
            o[1] = __floats2half2_rn(v.z, v.w);
        } else if (i < 4L * NW + NF) {
            long ii = i - 4L * NW;
            float4 v = ((const float4*)w1)[ii];
            __half2* o = (__half2*)(w1h + ii * 4);
            o[0] = __floats2half2_rn(v.x, v.y);
            o[1] = __floats2half2_rn(v.z, v.w);
        } else if (i < 4L * NW + 2L * NF) {
            long ii = i - 4L * NW - NF;
            float4 v = ((const float4*)w2)[ii];
            __half2* o = (__half2*)(w2h + ii * 4);
            o[0] = __floats2half2_rn(v.x, v.y);
            o[1] = __floats2half2_rn(v.z, v.w);
        } else {
            long ii = i - 4L * NW - 2L * NF;   // 0..767
            int jj = (int)ii * 4;
            const float* src = (jj < DD) ? bq : (jj < 2 * DD) ? bk : bv;
            *(float4*)(bqkv + jj) = *(const float4*)(src + (jj & (DD - 1)));
        }
    }
}

// ---------------- LayerNorm: one warp per row, shfl-only -------------------
__global__ void __launch_bounds__(256) ln_kernel(
    const float* __restrict__ x, const float* __restrict__ gw,
    const float* __restrict__ bw, __half* __restrict__ y)
{
    int warp = threadIdx.x >> 5, lane = threadIdx.x & 31;
    int row = blockIdx.x * 8 + warp;
    const float4* xr = (const float4*)(x + (size_t)row * DD);

    float4 v[8];
    float s = 0.f, ss = 0.f;
    #pragma unroll
    for (int i = 0; i < 8; i++) {
        v[i] = xr[lane + i * 32];
        s  += v[i].x + v[i].y + v[i].z + v[i].w;
        ss += v[i].x * v[i].x + v[i].y * v[i].y + v[i].z * v[i].z + v[i].w * v[i].w;
    }
    #pragma unroll
    for (int o = 16; o; o >>= 1) {
        s  += __shfl_xor_sync(0xffffffffu, s,  o);
        ss += __shfl_xor_sync(0xffffffffu, ss, o);
    }
    float mean = s * (1.0f / DD);
    float var  = (ss - s * s * (1.0f / DD)) * (1.0f / (DD - 1));
    var = fmaxf(var, 0.f);
    float rd = 1.0f / (sqrtf(var) + 1e-6f);

    __half2* yo = (__half2*)(y + (size_t)row * DD);
    #pragma unroll
    for (int i = 0; i < 8; i++) {
        float4 g4 = ((const float4*)gw)[lane + i * 32];
        float4 b4 = ((const float4*)bw)[lane + i * 32];
        yo[2 * (lane + i * 32)] =
            __floats2half2_rn(g4.x * (v[i].x - mean) * rd + b4.x,
                              g4.y * (v[i].y - mean) * rd + b4.y);
        yo[2 * (lane + i * 32) + 1] =
            __floats2half2_rn(g4.z * (v[i].z - mean) * rd + b4.z,
                              g4.w * (v[i].w - mean) * rd + b4.w);
    }
}

// ---------------- fp16 mma GEMM (128x128x64, 4 warps x 64x64, 2 CTA/SM) ----
// K-chunk 64, 3-stage pipeline: half the barriers of the k32/4-stage version.
#define TKH 64
#define ASTRH 72
#define BSTRH 136
#define A_TILE_H (128 * ASTRH)
#define B_TILE_H (TKH * BSTRH)
#define STAGE_H (A_TILE_H + B_TILE_H)
#define NSTG 3
#define GEMM_SMEM (NSTG * STAGE_H * 2)

// EPI: 1 = bias+gelu -> fp16 out, 2 = bias+residual -> fp32 out,
//      3 = bias -> fp16 out
template <int EPI>
__global__ void __launch_bounds__(128, 2) gemm_f16(
    const __half* __restrict__ A, const __half* __restrict__ W,
    const float* __restrict__ bias, const float* __restrict__ R,
    void* __restrict__ Cv, int M, int K, int N)
{
    extern __shared__ __half smh[];
    uint32_t sbase = smem_u32(smh);
    int t = threadIdx.x;
    int m0 = blockIdx.y * 128, n0 = blockIdx.x * 128;
    int nkt = K >> 6;

    auto load_tile = [&](int stg, int kt) {
        __half* As = smh + stg * STAGE_H;
        __half* Bs = As + A_TILE_H;
        int k0 = kt * TKH;
        #pragma unroll
        for (int i = 0; i < 8; i++) {
            int id = t + i * 128;
            int row = id >> 3, c8 = (id & 7) << 3;
            cp16(As + row * ASTRH + c8, A + (size_t)(m0 + row) * K + k0 + c8);
        }
        #pragma unroll
        for (int i = 0; i < 8; i++) {
            int id = t + i * 128;
            int row = id >> 4, c8 = (id & 15) << 3;
            cp16(Bs + row * BSTRH + c8, W + (size_t)(k0 + row) * N + n0 + c8);
        }
    };

    float acc[4][8][4];
    #pragma unroll
    for (int mt = 0; mt < 4; mt++)
        #pragma unroll
        for (int nt = 0; nt < 8; nt++)
            #pragma unroll
            for (int i = 0; i < 4; i++) acc[mt][nt][i] = 0.f;

    int lane = t & 31, wid = t >> 5;
    int warpM = wid >> 1, warpN = wid & 1;
    int g = lane >> 2, c = lane & 3;
    int arow_l = lane & 15;
    int acol_l = (lane >> 4) << 3;
    int mat = lane >> 3, lr = lane & 7;
    int bko = ((mat & 1) << 3) + lr;
    int bno = (mat >> 1) << 3;

    load_tile(0, 0); cp_commit();
    load_tile(1, 1); cp_commit();

    int stg = 0, lstg = 2;
    for (int kt = 0; kt < nkt; kt++) {
        cp_wait<1>();
        __syncthreads();

        if (kt + 2 < nkt) load_tile(lstg, kt + 2);
        cp_commit();

        uint32_t As_u = sbase + (uint32_t)(stg * STAGE_H) * 2;
        uint32_t Bs_u = As_u + A_TILE_H * 2;

        #pragma unroll
        for (int ks = 0; ks < 4; ks++) {
            uint32_t af[4][4];
            #pragma unroll
            for (int mt = 0; mt < 4; mt++)
                ldm_x4(af[mt], As_u +
                    ((uint32_t)((warpM * 64 + mt * 16 + arow_l) * ASTRH
                                + ks * 16 + acol_l) << 1));
            uint32_t b4[4][4];
            #pragma unroll
            for (int p = 0; p < 4; p++) {
                int bk = ks * 16 + bko;
                int bn = warpN * 64 + p * 16 + bno;
                ldm_x4t(b4[p], Bs_u + ((uint32_t)(bk * BSTRH + bn) << 1));
            }
            #pragma unroll
            for (int mt = 0; mt < 4; mt++)
                #pragma unroll
                for (int nt = 0; nt < 8; nt++)
                    mma16(acc[mt][nt], af[mt], &b4[nt >> 1][(nt & 1) << 1]);
        }

        if (++stg == NSTG) stg = 0;
        if (++lstg == NSTG) lstg = 0;
    }

    int rbase = m0 + warpM * 64 + g;
    int cbase = n0 + warpN * 64 + 2 * c;

    #pragma unroll
    for (int nt = 0; nt < 8; nt++) {
        int col = cbase + nt * 8;
        float2 b2 = *(const float2*)(bias + col);
        #pragma unroll
        for (int mt = 0; mt < 4; mt++) {
            int r0 = rbase + mt * 16;
            float v0x = acc[mt][nt][0] + b2.x;
            float v0y = acc[mt][nt][1] + b2.y;
            float v1x = acc[mt][nt][2] + b2.x;
            float v1y = acc[mt][nt][3] + b2.y;
            if (EPI == 2) {
                float* C = (float*)Cv;
                float2 r0v = *(const float2*)(R + (size_t)r0 * N + col);
                float2 r1v = *(const float2*)(R + (size_t)(r0 + 8) * N + col);
                *(float2*)(C + (size_t)r0 * N + col) =
                    make_float2(v0x + r0v.x, v0y + r0v.y);
                *(float2*)(C + (size_t)(r0 + 8) * N + col) =
                    make_float2(v1x + r1v.x, v1y + r1v.y);
            } else {
                if (EPI == 1) {
                    v0x = gelu_tanh_f(v0x); v0y = gelu_tanh_f(v0y);
                    v1x = gelu_tanh_f(v1x); v1y = gelu_tanh_f(v1y);
                }
                __half* C = (__half*)Cv;
                *(__half2*)(C + (size_t)r0 * N + col) = __floats2half2_rn(v0x, v0y);
                *(__half2*)(C + (size_t)(r0 + 8) * N + col) = __floats2half2_rn(v1x, v1y);
            }
        }
    }
}

// ---------------- fp16 tensor-core flash attention (round-11 config) --------
#define FQSTR 72
#define FQ_H (128 * FQSTR)
#define FKV_H (64 * FQSTR)
#define KOFF FQ_H
#define VOFF (FQ_H + 4 * FKV_H)
#define MOFF_BYTES ((FQ_H + 8 * FKV_H) * 2)
#define FLASH_SMEM (MOFF_BYTES + 4 * 64 * 4 + 16)
#define QSCALE 0.1803368801111204f   /* 0.125 * log2(e) */
#define MBIAS  (-1.44269504e9f)      /* -1e9 * log2(e)  */

__global__ void __launch_bounds__(128, 2) flash_f16(
    const __half* __restrict__ Q, const __half* __restrict__ Kg,
    const __half* __restrict__ Vg, int ldq, const int* __restrict__ mask,
    __half* __restrict__ O)
{
    extern __shared__ __half smh[];
    uint32_t sbase = smem_u32(smh);
    int* mksm = (int*)((char*)smh + MOFF_BYTES);
    int t = threadIdx.x;
    int lane = t & 31, wid = t >> 5;
    int g = lane >> 2, c = lane & 3;
    int q0 = blockIdx.x * 128;
    int h = blockIdx.y, b = blockIdx.z;
    size_t baseQ = ((size_t)(b * SS + q0)) * ldq + h * DHD;

    auto load_kv = [&](int kt, int s) {
        size_t baseK = ((size_t)(b * SS + kt * 64)) * ldq + h * DHD;
        __half* Kb = smh + KOFF + s * FKV_H;
        __half* Vb = smh + VOFF + s * FKV_H;
        #pragma unroll
        for (int i = 0; i < 4; i++) {
            int id = t + i * 128;
            int row = id >> 3, c8 = (id & 7) << 3;
            cp16(Kb + row * FQSTR + c8, Kg + baseK + (size_t)row * ldq + c8);
            cp16(Vb + row * FQSTR + c8, Vg + baseK + (size_t)row * ldq + c8);
        }
        if (t < 16) cp16(mksm + s * 64 + t * 4, mask + b * SS + kt * 64 + t * 4);
    };

    load_kv(0, 0);
    #pragma unroll
    for (int i = 0; i < 8; i++) {
        int id = t + i * 128;
        int row = id >> 3, c8 = (id & 7) << 3;
        cp16(smh + row * FQSTR + c8, Q + baseQ + (size_t)row * ldq + c8);
    }
    cp_commit();
    load_kv(1, 1);
    cp_commit();
    load_kv(2, 2);
    cp_commit();

    cp_wait<2>();
    __syncthreads();

    int arow_l = lane & 15;
    int acol_l = (lane >> 4) << 3;
    int mat = lane >> 3, lr = lane & 7;
    uint32_t qf[2][4][4];
    int qb = wid * 32;
    {
        __half2 qs = __float2half2_rn(QSCALE);
        #pragma unroll
        for (int mt = 0; mt < 2; mt++)
            #pragma unroll
            for (int ks = 0; ks < 4; ks++) {
                ldm_x4(qf[mt][ks], sbase +
                    ((uint32_t)((qb + mt * 16 + arow_l) * FQSTR
                                + ks * 16 + acol_l) << 1));
                #pragma unroll
                for (int i = 0; i < 4; i++) {
                    __half2 hv = *(__half2*)&qf[mt][ks][i];
                    hv = __hmul2(hv, qs);
                    qf[mt][ks][i] = *(uint32_t*)&hv;
                }
            }
    }

    float m0[2], m1[2], l0[2], l1[2];
    #pragma unroll
    for (int mt = 0; mt < 2; mt++) {
        m0[mt] = -1e30f; m1[mt] = -1e30f; l0[mt] = 0.f; l1[mt] = 0.f;
    }
    float acc[2][8][4];
    #pragma unroll
    for (int mt = 0; mt < 2; mt++)
        #pragma unroll
        for (int nt = 0; nt < 8; nt++)
            #pragma unroll
            for (int i = 0; i < 4; i++) acc[mt][nt][i] = 0.f;

    uint32_t kfrag_base = sbase + ((uint32_t)(((mat >> 1) << 3) + lr) * FQSTR
                                   + ((mat & 1) << 3)) * 2 + KOFF * 2;
    uint32_t vfrag_base = sbase + ((uint32_t)((((mat & 1) << 3) + lr) * FQSTR)
                                   + (((mat >> 1) << 3))) * 2 + VOFF * 2;

    for (int kto = 0; kto < SS / 64; kto += 4) {
        #pragma unroll
        for (int st = 0; st < 4; st++) {
            int kt = kto + st;
            cp_wait<2>();
            __syncthreads();

            int nx = kt + 3;
            if (nx < SS / 64) load_kv(nx, nx & 3);
            cp_commit();

            const int* mk = mksm + st * 64;

            float sf[2][8][4];
            #pragma unroll
            for (int mt = 0; mt < 2; mt++)
                #pragma unroll
                for (int nt = 0; nt < 8; nt++)
                    #pragma unroll
                    for (int i = 0; i < 4; i++) sf[mt][nt][i] = 0.f;

            #pragma unroll
            for (int ks = 0; ks < 4; ks++) {
                #pragma unroll
                for (int p = 0; p < 4; p++) {
                    uint32_t kb[4];
                    ldm_x4(kb, kfrag_base + (uint32_t)(st * FKV_H * 2)
                               + (uint32_t)((p * 16 * FQSTR + ks * 16) << 1));
                    #pragma unroll
                    for (int mt = 0; mt < 2; mt++) {
                        mma16(sf[mt][2 * p],     qf[mt][ks], kb);
                        mma16(sf[mt][2 * p + 1], qf[mt][ks], kb + 2);
                    }
                }
            }

            #pragma unroll
            for (int mt = 0; mt < 2; mt++) {
                float mx0 = -1e30f, mx1 = -1e30f;
                #pragma unroll
                for (int nt = 0; nt < 8; nt++) {
                    float bia0 = mk[nt * 8 + 2 * c]     ? 0.f : MBIAS;
                    float bia1 = mk[nt * 8 + 2 * c + 1] ? 0.f : MBIAS;
                    sf[mt][nt][0] += bia0; sf[mt][nt][1] += bia1;
                    sf[mt][nt][2] += bia0; sf[mt][nt][3] += bia1;
                    mx0 = fmaxf(mx0, fmaxf(sf[mt][nt][0], sf[mt][nt][1]));
                    mx1 = fmaxf(mx1, fmaxf(sf[mt][nt][2], sf[mt][nt][3]));
                }
                mx0 = fmaxf(mx0, __shfl_xor_sync(0xffffffffu, mx0, 1));
                mx0 = fmaxf(mx0, __shfl_xor_sync(0xffffffffu, mx0, 2));
                mx1 = fmaxf(mx1, __shfl_xor_sync(0xffffffffu, mx1, 1));
                mx1 = fmaxf(mx1, __shfl_xor_sync(0xffffffffu, mx1, 2));

                float mn0 = fmaxf(m0[mt], mx0), mn1 = fmaxf(m1[mt], mx1);
                float al0 = ex2f(m0[mt] - mn0), al1 = ex2f(m1[mt] - mn1);
                m0[mt] = mn0; m1[mt] = mn1;

                float ps0 = 0.f, ps1 = 0.f;
                #pragma unroll
                for (int nt = 0; nt < 8; nt++) {
                    sf[mt][nt][0] = ex2f(sf[mt][nt][0] - mn0);
                    sf[mt][nt][1] = ex2f(sf[mt][nt][1] - mn0);
                    sf[mt][nt][2] = ex2f(sf[mt][nt][2] - mn1);
                    sf[mt][nt][3] = ex2f(sf[mt][nt][3] - mn1);
                    ps0 += sf[mt][nt][0] + sf[mt][nt][1];
                    ps1 += sf[mt][nt][2] + sf[mt][nt][3];
                }
                ps0 += __shfl_xor_sync(0xffffffffu, ps0, 1);
                ps0 += __shfl_xor_sync(0xffffffffu, ps0, 2);
                ps1 += __shfl_xor_sync(0xffffffffu, ps1, 1);
                ps1 += __shfl_xor_sync(0xffffffffu, ps1, 2);
                l0[mt] = l0[mt] * al0 + ps0;
                l1[mt] = l1[mt] * al1 + ps1;

                #pragma unroll
                for (int nt = 0; nt < 8; nt++) {
                    acc[mt][nt][0] *= al0; acc[mt][nt][1] *= al0;
                    acc[mt][nt][2] *= al1; acc[mt][nt][3] *= al1;
                }
            }

            #pragma unroll
            for (int ks = 0; ks < 4; ks++) {
                uint32_t af[2][4];
                #pragma unroll
                for (int mt = 0; mt < 2; mt++) {
                    af[mt][0] = packh2(sf[mt][2 * ks][0],     sf[mt][2 * ks][1]);
                    af[mt][1] = packh2(sf[mt][2 * ks][2],     sf[mt][2 * ks][3]);
                    af[mt][2] = packh2(sf[mt][2 * ks + 1][0], sf[mt][2 * ks + 1][1]);
                    af[mt][3] = packh2(sf[mt][2 * ks + 1][2], sf[mt][2 * ks + 1][3]);
                }
                #pragma unroll
                for (int p = 0; p < 4; p++) {
                    uint32_t vb[4];
                    ldm_x4t(vb, vfrag_base + (uint32_t)(st * FKV_H * 2)
                                + (uint32_t)((ks * 16 * FQSTR + p * 16) << 1));
                    #pragma unroll
                    for (int mt = 0; mt < 2; mt++) {
                        mma16(acc[mt][2 * p],     af[mt], vb);
                        mma16(acc[mt][2 * p + 1], af[mt], vb + 2);
                    }
                }
            }
        }
    }

    #pragma unroll
    for (int mt = 0; mt < 2; mt++) {
        float inv0 = 1.f / l0[mt], inv1 = 1.f / l1[mt];
        size_t r0 = ((size_t)(b * SS + q0 + qb + mt * 16 + g)) * DD + h * DHD;
        size_t r1 = r0 + 8 * DD;
        #pragma unroll
        for (int nt = 0; nt < 8; nt++) {
            int col = nt * 8 + 2 * c;
            *(__half2*)(O + r0 + col) =
                __floats2half2_rn(acc[mt][nt][0] * inv0, acc[mt][nt][1] * inv0);
            *(__half2*)(O + r1 + col) =
                __floats2half2_rn(acc[mt][nt][2] * inv1, acc[mt][nt][3] * inv1);
        }
    }
}

// ---------------- launch ---------------------------------------------------
extern "C" void kernel_launch(void* const* d_in, const int* in_sizes, int n_in,
                              void* d_out, int out_size)
{
    const float* hidden = (const float*)d_in[0];
    const int*   mask   = (const int*)d_in[1];
    const float* wq = (const float*)d_in[2];
    const float* bq = (const float*)d_in[3];
    const float* wk = (const float*)d_in[4];
    const float* bk = (const float*)d_in[5];
    const float* wv = (const float*)d_in[6];
    const float* bv = (const float*)d_in[7];
    const float* wo = (const float*)d_in[8];
    const float* bo = (const float*)d_in[9];
    const float* w1 = (const float*)d_in[10];
    const float* b1 = (const float*)d_in[11];
    const float* w2 = (const float*)d_in[12];
    const float* b2 = (const float*)d_in[13];
    const float* ln1_g = (const float*)d_in[14];
    const float* ln1_b = (const float*)d_in[15];
    const float* ln2_g = (const float*)d_in[16];
    const float* ln2_b = (const float*)d_in[17];
    float* out = (float*)d_out;

    __half *ln, *qkv, *attn, *f1, *wqkvh, *woh, *w1h, *w2h;
    float *h1, *bqkv;
    cudaGetSymbolAddress((void**)&ln,    g_ln);
    cudaGetSymbolAddress((void**)&qkv,   g_qkv);
    cudaGetSymbolAddress((void**)&attn,  g_attn);
    cudaGetSymbolAddress((void**)&h1,    g_h1);
    cudaGetSymbolAddress((void**)&f1,    g_f1);
    cudaGetSymbolAddress((void**)&wqkvh, g_wqkv);
    cudaGetSymbolAddress((void**)&bqkv,  g_bqkv);
    cudaGetSymbolAddress((void**)&woh,   g_wo);
    cudaGetSymbolAddress((void**)&w1h,   g_w1);
    cudaGetSymbolAddress((void**)&w2h,   g_w2);

    cudaFuncSetAttribute(flash_f16,
                         cudaFuncAttributeMaxDynamicSharedMemorySize, FLASH_SMEM);
    cudaFuncSetAttribute(gemm_f16<1>,
                         cudaFuncAttributeMaxDynamicSharedMemorySize, GEMM_SMEM);
    cudaFuncSetAttribute(gemm_f16<2>,
                         cudaFuncAttributeMaxDynamicSharedMemorySize, GEMM_SMEM);
    cudaFuncSetAttribute(gemm_f16<3>,
                         cudaFuncAttributeMaxDynamicSharedMemorySize, GEMM_SMEM);

    // one fused pack launch (8 float4 in flight per thread)
    pack_all<<<(unsigned)PACK_BLOCKS, 256>>>(wq, wk, wv, wo, w1, w2, bq, bk, bv,
                                             wqkvh, woh, w1h, w2h, bqkv);

    // 1) LN1 (warp-per-row)
    ln_kernel<<<NROWS / 8, 256>>>(hidden, ln1_g, ln1_b, ln);

    // 2) fused QKV projection -> fp16
    dim3 gQKV(NQKV / 128, NROWS / 128);
    gemm_f16<3><<<gQKV, 128, GEMM_SMEM>>>(ln, wqkvh, bqkv, nullptr, qkv,
                                          NROWS, DD, NQKV);

    // 3) attention
    flash_f16<<<dim3(SS / 128, HH, BB), 128, FLASH_SMEM>>>(
        qkv, qkv + DD, qkv + 2 * DD, NQKV, mask, attn);

    // 4) output projection + residual -> fp32
    dim3 gD(DD / 128, NROWS / 128);
    gemm_f16<2><<<gD, 128, GEMM_SMEM>>>(attn, woh, bo, hidden, h1, NROWS, DD, DD);

    // 5) LN2
    ln_kernel<<<NROWS / 8, 256>>>(h1, ln2_g, ln2_b, ln);

    // 6) FFN
    dim3 gF(DFF / 128, NROWS / 128);
    gemm_f16<1><<<gF, 128, GEMM_SMEM>>>(ln, w1h, b1, nullptr, f1, NROWS, DD, DFF);
    gemm_f16<2><<<gD, 128, GEMM_SMEM>>>(f1, w2h, b2, h1, out, NROWS, DFF, DD);
}

// round 13
// speedup vs baseline: 1.1203x; 1.1203x over previous
#include <cuda_runtime.h>
#include <cuda_fp16.h>
#include <math.h>
#include <stdint.h>

#define BB 2
#define SS 2048
#define DD 1024
#define HH 16
#define DHD 64
#define DFF 4096
#define NROWS (BB * SS)
#define NQKV 3072

// ---------------- scratch (device globals; no allocation) ----------------
__device__ __half g_ln[NROWS * DD];
__device__ __half g_qkv[NROWS * NQKV];
__device__ __half g_attn[NROWS * DD];
__device__ float  g_h1[NROWS * DD];
__device__ __half g_f1[NROWS * DFF];
__device__ __half g_wqkv[DD * NQKV];
__device__ float  g_bqkv[NQKV];
__device__ __half g_wo[DD * DD];
__device__ __half g_w1[DD * DFF];
__device__ __half g_w2[DFF * DD];

// ---------------- helpers --------------------------------------------------
__device__ __forceinline__ uint32_t smem_u32(const void* p) {
    uint32_t a;
    asm("{ .reg .u64 t; cvta.to.shared.u64 t, %1; cvt.u32.u64 %0, t; }" : "=r"(a) : "l"(p));
    return a;
}
__device__ __forceinline__ void cp16(void* dst_smem, const void* src) {
    uint32_t d;
    asm("{ .reg .u64 t; cvta.to.shared.u64 t, %1; cvt.u32.u64 %0, t; }"
        : "=r"(d) : "l"(dst_smem));
    asm volatile("cp.async.cg.shared.global [%0], [%1], 16;" :: "r"(d), "l"(src));
}
__device__ __forceinline__ void cp_commit() {
    asm volatile("cp.async.commit_group;");
}
template <int N>
__device__ __forceinline__ void cp_wait() {
    asm volatile("cp.async.wait_group %0;" :: "n"(N));
}
__device__ __forceinline__ void ldm_x4(uint32_t r[4], uint32_t addr) {
    asm volatile("ldmatrix.sync.aligned.m8n8.x4.shared.b16 {%0,%1,%2,%3}, [%4];"
        : "=r"(r[0]), "=r"(r[1]), "=r"(r[2]), "=r"(r[3]) : "r"(addr));
}
__device__ __forceinline__ void ldm_x4t(uint32_t r[4], uint32_t addr) {
    asm volatile("ldmatrix.sync.aligned.m8n8.x4.trans.shared.b16 {%0,%1,%2,%3}, [%4];"
        : "=r"(r[0]), "=r"(r[1]), "=r"(r[2]), "=r"(r[3]) : "r"(addr));
}
__device__ __forceinline__ void mma16(float c[4], const uint32_t a[4], const uint32_t b[2]) {
    asm volatile(
        "mma.sync.aligned.m16n8k16.row.col.f32.f16.f16.f32 "
        "{%0,%1,%2,%3}, {%4,%5,%6,%7}, {%8,%9}, {%0,%1,%2,%3};"
        : "+f"(c[0]), "+f"(c[1]), "+f"(c[2]), "+f"(c[3])
        : "r"(a[0]), "r"(a[1]), "r"(a[2]), "r"(a[3]), "r"(b[0]), "r"(b[1]));
}
__device__ __forceinline__ uint32_t packh2(float lo, float hi) {
    __half2 h = __floats2half2_rn(lo, hi);
    return *(uint32_t*)&h;
}
__device__ __forceinline__ float ex2f(float x) {
    float r;
    asm("ex2.approx.f32 %0, %1;" : "=f"(r) : "f"(x));
    return r;
}
__device__ __forceinline__ float gelu_tanh_f(float h) {
    const float c = 0.7978845608028654f;
    float u = c * (h + 0.044715f * h * h * h);
    return 0.5f * h * (1.0f + tanhf(u));
}

// ---------------- ONE fused pack kernel, 8 float4 in flight per thread -----
#define NW (DD * DD / 4)
#define NF (DD * DFF / 4)
#define PACK_TOT (4L * NW + 2L * NF + 768)
#define PACK_BLOCKS ((PACK_TOT + 2047) / 2048)
__global__ void __launch_bounds__(256) pack_all(
    const float* __restrict__ wq, const float* __restrict__ wk,
    const float* __restrict__ wv, const float* __restrict__ wo,
    const float* __restrict__ w1, const float* __restrict__ w2,
    const float* __restrict__ bq, const float* __restrict__ bk,
    const float* __restrict__ bv,
    __half* __restrict__ wqkv, __half* __restrict__ woh,
    __half* __restrict__ w1h, __half* __restrict__ w2h,
    float* __restrict__ bqkv)
{
    #pragma unroll
    for (int j = 0; j < 8; j++) {
        long i = (long)blockIdx.x * 2048 + j * 256 + threadIdx.x;
        if (i >= PACK_TOT) break;
        if (i < 3L * NW) {
            const float* src = (i < NW) ? wq : (i < 2L * NW) ? wk : wv;
            int coff = (i < NW) ? 0 : (i < 2L * NW) ? DD : 2 * DD;
            long ii = i % NW;
            int row = (int)(ii >> 8), c4 = ((int)ii & 255) << 2;
            float4 v = ((const float4*)src)[ii];
            __half2* o = (__half2*)(wqkv + (size_t)row * NQKV + coff + c4);
            o[0] = __floats2half2_rn(v.x, v.y);
            o[1] = __floats2half2_rn(v.z, v.w);
        } else if (i < 4L * NW) {
            long ii = i - 3L * NW;
            float4 v = ((const float4*)wo)[ii];
            __half2* o = (__half2*)(woh + ii * 4);
            o[0] = __floats2half2_rn(v.x, v.y);
            o[1] = __floats2half2_rn(v.z, v.w);
        } else if (i < 4L * NW + NF) {
            long ii = i - 4L * NW;
            float4 v = ((const float4*)w1)[ii];
            __half2* o = (__half2*)(w1h + ii * 4);
            o[0] = __floats2half2_rn(v.x, v.y);
            o[1] = __floats2half2_rn(v.z, v.w);
        } else if (i < 4L * NW + 2L * NF) {
            long ii = i - 4L * NW - NF;
            float4 v = ((const float4*)w2)[ii];
            __half2* o = (__half2*)(w2h + ii * 4);
            o[0] = __floats2half2_rn(v.x, v.y);
            o[1] = __floats2half2_rn(v.z, v.w);
        } else {
            long ii = i - 4L * NW - 2L * NF;   // 0..767
            int jj = (int)ii * 4;
            const float* src = (jj < DD) ? bq : (jj < 2 * DD) ? bk : bv;
            *(float4*)(bqkv + jj) = *(const float4*)(src + (jj & (DD - 1)));
        }
    }
}

// ---------------- LayerNorm: one warp per row, shfl-only -------------------
__global__ void __launch_bounds__(256) ln_kernel(
    const float* __restrict__ x, const float* __restrict__ gw,
    const float* __restrict__ bw, __half* __restrict__ y)
{
    int warp = threadIdx.x >> 5, lane = threadIdx.x & 31;
    int row = blockIdx.x * 8 + warp;
    const float4* xr = (const float4*)(x + (size_t)row * DD);

    float4 v[8];
    float s = 0.f, ss = 0.f;
    #pragma unroll
    for (int i = 0; i < 8; i++) {
        v[i] = xr[lane + i * 32];
        s  += v[i].x + v[i].y + v[i].z + v[i].w;
        ss += v[i].x * v[i].x + v[i].y * v[i].y + v[i].z * v[i].z + v[i].w * v[i].w;
    }
    #pragma unroll
    for (int o = 16; o; o >>= 1) {
        s  += __shfl_xor_sync(0xffffffffu, s,  o);
        ss += __shfl_xor_sync(0xffffffffu, ss, o);
    }
    float mean = s * (1.0f / DD);
    float var  = (ss - s * s * (1.0f / DD)) * (1.0f / (DD - 1));
    var = fmaxf(var, 0.f);
    float rd = 1.0f / (sqrtf(var) + 1e-6f);

    __half2* yo = (__half2*)(y + (size_t)row * DD);
    #pragma unroll
    for (int i = 0; i < 8; i++) {
        float4 g4 = ((const float4*)gw)[lane + i * 32];
        float4 b4 = ((const float4*)bw)[lane + i * 32];
        yo[2 * (lane + i * 32)] =
            __floats2half2_rn(g4.x * (v[i].x - mean) * rd + b4.x,
                              g4.y * (v[i].y - mean) * rd + b4.y);
        yo[2 * (lane + i * 32) + 1] =
            __floats2half2_rn(g4.z * (v[i].z - mean) * rd + b4.z,
                              g4.w * (v[i].w - mean) * rd + b4.w);
    }
}

// ---------------- fp16 mma GEMM (128x128x32, 4 warps x 64x64, 2 CTA/SM) ----
// Round-11 winning config: TKH=32, NSTG=4, static stage indexing.
#define TKH 32
#define ASTRH 40
#define BSTRH 136
#define A_TILE_H (128 * ASTRH)
#define B_TILE_H (TKH * BSTRH)
#define STAGE_H (A_TILE_H + B_TILE_H)
#define NSTG 4
#define GEMM_SMEM (NSTG * STAGE_H * 2)

// EPI: 1 = bias+gelu -> fp16 out, 2 = bias+residual -> fp32 out,
//      3 = bias -> fp16 out
template <int EPI>
__global__ void __launch_bounds__(128, 2) gemm_f16(
    const __half* __restrict__ A, const __half* __restrict__ W,
    const float* __restrict__ bias, const float* __restrict__ R,
    void* __restrict__ Cv, int M, int K, int N)
{
    extern __shared__ __half smh[];
    uint32_t sbase = smem_u32(smh);
    int t = threadIdx.x;
    int m0 = blockIdx.y * 128, n0 = blockIdx.x * 128;
    int nkt = K >> 5;

    auto load_tile = [&](int stg, int kt) {
        __half* As = smh + stg * STAGE_H;
        __half* Bs = As + A_TILE_H;
        int k0 = kt * TKH;
        #pragma unroll
        for (int i = 0; i < 4; i++) {
            int id = t + i * 128;
            int row = id >> 2, c8 = (id & 3) << 3;
            cp16(As + row * ASTRH + c8, A + (size_t)(m0 + row) * K + k0 + c8);
        }
        #pragma unroll
        for (int i = 0; i < 4; i++) {
            int id = t + i * 128;
            int row = id >> 4, c8 = (id & 15) << 3;
            cp16(Bs + row * BSTRH + c8, W + (size_t)(k0 + row) * N + n0 + c8);
        }
    };

    float acc[4][8][4];
    #pragma unroll
    for (int mt = 0; mt < 4; mt++)
        #pragma unroll
        for (int nt = 0; nt < 8; nt++)
            #pragma unroll
            for (int i = 0; i < 4; i++) acc[mt][nt][i] = 0.f;

    int lane = t & 31, wid = t >> 5;
    int warpM = wid >> 1, warpN = wid & 1;
    int g = lane >> 2, c = lane & 3;
    int arow_l = lane & 15;
    int acol_l = (lane >> 4) << 3;
    int mat = lane >> 3, lr = lane & 7;
    int bko = ((mat & 1) << 3) + lr;
    int bno = (mat >> 1) << 3;

    #pragma unroll
    for (int s = 0; s < NSTG - 1; s++) { load_tile(s, s); cp_commit(); }

    for (int kt = 0; kt < nkt; kt++) {
        cp_wait<NSTG - 2>();
        __syncthreads();

        int nx = kt + NSTG - 1;
        if (nx < nkt) load_tile(nx & (NSTG - 1), nx);
        cp_commit();

        uint32_t As_u = sbase + (uint32_t)((kt & (NSTG - 1)) * STAGE_H) * 2;
        uint32_t Bs_u = As_u + A_TILE_H * 2;

        #pragma unroll
        for (int ks = 0; ks < 2; ks++) {
            uint32_t af[4][4];
            #pragma unroll
            for (int mt = 0; mt < 4; mt++)
                ldm_x4(af[mt], As_u +
                    ((uint32_t)((warpM * 64 + mt * 16 + arow_l) * ASTRH
                                + ks * 16 + acol_l) << 1));
            uint32_t b4[4][4];
            #pragma unroll
            for (int p = 0; p < 4; p++) {
                int bk = ks * 16 + bko;
                int bn = warpN * 64 + p * 16 + bno;
                ldm_x4t(b4[p], Bs_u + ((uint32_t)(bk * BSTRH + bn) << 1));
            }
            #pragma unroll
            for (int mt = 0; mt < 4; mt++)
                #pragma unroll
                for (int nt = 0; nt < 8; nt++)
                    mma16(acc[mt][nt], af[mt], &b4[nt >> 1][(nt & 1) << 1]);
        }
    }

    int rbase = m0 + warpM * 64 + g;
    int cbase = n0 + warpN * 64 + 2 * c;

    #pragma unroll
    for (int nt = 0; nt < 8; nt++) {
        int col = cbase + nt * 8;
        float2 b2 = *(const float2*)(bias + col);
        #pragma unroll
        for (int mt = 0; mt < 4; mt++) {
            int r0 = rbase + mt * 16;
            float v0x = acc[mt][nt][0] + b2.x;
            float v0y = acc[mt][nt][1] + b2.y;
            float v1x = acc[mt][nt][2] + b2.x;
            float v1y = acc[mt][nt][3] + b2.y;
            if (EPI == 2) {
                float* C = (float*)Cv;
                float2 r0v = *(const float2*)(R + (size_t)r0 * N + col);
                float2 r1v = *(const float2*)(R + (size_t)(r0 + 8) * N + col);
                *(float2*)(C + (size_t)r0 * N + col) =
                    make_float2(v0x + r0v.x, v0y + r0v.y);
                *(float2*)(C + (size_t)(r0 + 8) * N + col) =
                    make_float2(v1x + r1v.x, v1y + r1v.y);
            } else {
                if (EPI == 1) {
                    v0x = gelu_tanh_f(v0x); v0y = gelu_tanh_f(v0y);
                    v1x = gelu_tanh_f(v1x); v1y = gelu_tanh_f(v1y);
                }
                __half* C = (__half*)Cv;
                *(__half2*)(C + (size_t)r0 * N + col) = __floats2half2_rn(v0x, v0y);
                *(__half2*)(C + (size_t)(r0 + 8) * N + col) = __floats2half2_rn(v1x, v1y);
            }
        }
    }
}

// ---------------- fp16 tensor-core flash attention (round-11 config) --------
#define FQSTR 72
#define FQ_H (128 * FQSTR)
#define FKV_H (64 * FQSTR)
#define KOFF FQ_H
#define VOFF (FQ_H + 4 * FKV_H)
#define MOFF_BYTES ((FQ_H + 8 * FKV_H) * 2)
#define FLASH_SMEM (MOFF_BYTES + 4 * 64 * 4 + 16)
#define QSCALE 0.1803368801111204f   /* 0.125 * log2(e) */
#define MBIAS  (-1.44269504e9f)      /* -1e9 * log2(e)  */

__global__ void __launch_bounds__(128, 2) flash_f16(
    const __half* __restrict__ Q, const __half* __restrict__ Kg,
    const __half* __restrict__ Vg, int ldq, const int* __restrict__ mask,
    __half* __restrict__ O)
{
    extern __shared__ __half smh[];
    uint32_t sbase = smem_u32(smh);
    int* mksm = (int*)((char*)smh + MOFF_BYTES);
    int t = threadIdx.x;
    int lane = t & 31, wid = t >> 5;
    int g = lane >> 2, c = lane & 3;
    int q0 = blockIdx.x * 128;
    int h = blockIdx.y, b = blockIdx.z;
    size_t baseQ = ((size_t)(b * SS + q0)) * ldq + h * DHD;

    auto load_kv = [&](int kt, int s) {
        size_t baseK = ((size_t)(b * SS + kt * 64)) * ldq + h * DHD;
        __half* Kb = smh + KOFF + s * FKV_H;
        __half* Vb = smh + VOFF + s * FKV_H;
        #pragma unroll
        for (int i = 0; i < 4; i++) {
            int id = t + i * 128;
            int row = id >> 3, c8 = (id & 7) << 3;
            cp16(Kb + row * FQSTR + c8, Kg + baseK + (size_t)row * ldq + c8);
            cp16(Vb + row * FQSTR + c8, Vg + baseK + (size_t)row * ldq + c8);
        }
        if (t < 16) cp16(mksm + s * 64 + t * 4, mask + b * SS + kt * 64 + t * 4);
    };

    load_kv(0, 0);
    #pragma unroll
    for (int i = 0; i < 8; i++) {
        int id = t + i * 128;
        int row = id >> 3, c8 = (id & 7) << 3;
        cp16(smh + row * FQSTR + c8, Q + baseQ + (size_t)row * ldq + c8);
    }
    cp_commit();
    load_kv(1, 1);
    cp_commit();
    load_kv(2, 2);
    cp_commit();

    cp_wait<2>();
    __syncthreads();

    int arow_l = lane & 15;
    int acol_l = (lane >> 4) << 3;
    int mat = lane >> 3, lr = lane & 7;
    uint32_t qf[2][4][4];
    int qb = wid * 32;
    {
        __half2 qs = __float2half2_rn(QSCALE);
        #pragma unroll
        for (int mt = 0; mt < 2; mt++)
            #pragma unroll
            for (int ks = 0; ks < 4; ks++) {
                ldm_x4(qf[mt][ks], sbase +
                    ((uint32_t)((qb + mt * 16 + arow_l) * FQSTR
                                + ks * 16 + acol_l) << 1));
                #pragma unroll
                for (int i = 0; i < 4; i++) {
                    __half2 hv = *(__half2*)&qf[mt][ks][i];
                    hv = __hmul2(hv, qs);
                    qf[mt][ks][i] = *(uint32_t*)&hv;
                }
            }
    }

    float m0[2], m1[2], l0[2], l1[2];
    #pragma unroll
    for (int mt = 0; mt < 2; mt++) {
        m0[mt] = -1e30f; m1[mt] = -1e30f; l0[mt] = 0.f; l1[mt] = 0.f;
    }
    float acc[2][8][4];
    #pragma unroll
    for (int mt = 0; mt < 2; mt++)
        #pragma unroll
        for (int nt = 0; nt < 8; nt++)
            #pragma unroll
            for (int i = 0; i < 4; i++) acc[mt][nt][i] = 0.f;

    uint32_t kfrag_base = sbase + ((uint32_t)(((mat >> 1) << 3) + lr) * FQSTR
                                   + ((mat & 1) << 3)) * 2 + KOFF * 2;
    uint32_t vfrag_base = sbase + ((uint32_t)((((mat & 1) << 3) + lr) * FQSTR)
                                   + (((mat >> 1) << 3))) * 2 + VOFF * 2;

    for (int kto = 0; kto < SS / 64; kto += 4) {
        #pragma unroll
        for (int st = 0; st < 4; st++) {
            int kt = kto + st;
            cp_wait<2>();
            __syncthreads();

            int nx = kt + 3;
            if (nx < SS / 64) load_kv(nx, nx & 3);
            cp_commit();

            const int* mk = mksm + st * 64;

            float sf[2][8][4];
            #pragma unroll
            for (int mt = 0; mt < 2; mt++)
                #pragma unroll
                for (int nt = 0; nt < 8; nt++)
                    #pragma unroll
                    for (int i = 0; i < 4; i++) sf[mt][nt][i] = 0.f;

            #pragma unroll
            for (int ks = 0; ks < 4; ks++) {
                #pragma unroll
                for (int p = 0; p < 4; p++) {
                    uint32_t kb[4];
                    ldm_x4(kb, kfrag_base + (uint32_t)(st * FKV_H * 2)
                               + (uint32_t)((p * 16 * FQSTR + ks * 16) << 1));
                    #pragma unroll
                    for (int mt = 0; mt < 2; mt++) {
                        mma16(sf[mt][2 * p],     qf[mt][ks], kb);
                        mma16(sf[mt][2 * p + 1], qf[mt][ks], kb + 2);
                    }
                }
            }

            #pragma unroll
            for (int mt = 0; mt < 2; mt++) {
                float mx0 = -1e30f, mx1 = -1e30f;
                #pragma unroll
                for (int nt = 0; nt < 8; nt++) {
                    float bia0 = mk[nt * 8 + 2 * c]     ? 0.f : MBIAS;
                    float bia1 = mk[nt * 8 + 2 * c + 1] ? 0.f : MBIAS;
                    sf[mt][nt][0] += bia0; sf[mt][nt][1] += bia1;
                    sf[mt][nt][2] += bia0; sf[mt][nt][3] += bia1;
                    mx0 = fmaxf(mx0, fmaxf(sf[mt][nt][0], sf[mt][nt][1]));
                    mx1 = fmaxf(mx1, fmaxf(sf[mt][nt][2], sf[mt][nt][3]));
                }
                mx0 = fmaxf(mx0, __shfl_xor_sync(0xffffffffu, mx0, 1));
                mx0 = fmaxf(mx0, __shfl_xor_sync(0xffffffffu, mx0, 2));
                mx1 = fmaxf(mx1, __shfl_xor_sync(0xffffffffu, mx1, 1));
                mx1 = fmaxf(mx1, __shfl_xor_sync(0xffffffffu, mx1, 2));

                float mn0 = fmaxf(m0[mt], mx0), mn1 = fmaxf(m1[mt], mx1);
                float al0 = ex2f(m0[mt] - mn0), al1 = ex2f(m1[mt] - mn1);
                m0[mt] = mn0; m1[mt] = mn1;

                float ps0 = 0.f, ps1 = 0.f;
                #pragma unroll
                for (int nt = 0; nt < 8; nt++) {
                    sf[mt][nt][0] = ex2f(sf[mt][nt][0] - mn0);
                    sf[mt][nt][1] = ex2f(sf[mt][nt][1] - mn0);
                    sf[mt][nt][2] = ex2f(sf[mt][nt][2] - mn1);
                    sf[mt][nt][3] = ex2f(sf[mt][nt][3] - mn1);
                    ps0 += sf[mt][nt][0] + sf[mt][nt][1];
                    ps1 += sf[mt][nt][2] + sf[mt][nt][3];
                }
                ps0 += __shfl_xor_sync(0xffffffffu, ps0, 1);
                ps0 += __shfl_xor_sync(0xffffffffu, ps0, 2);
                ps1 += __shfl_xor_sync(0xffffffffu, ps1, 1);
                ps1 += __shfl_xor_sync(0xffffffffu, ps1, 2);
                l0[mt] = l0[mt] * al0 + ps0;
                l1[mt] = l1[mt] * al1 + ps1;

                #pragma unroll
                for (int nt = 0; nt < 8; nt++) {
                    acc[mt][nt][0] *= al0; acc[mt][nt][1] *= al0;
                    acc[mt][nt][2] *= al1; acc[mt][nt][3] *= al1;
                }
            }

            #pragma unroll
            for (int ks = 0; ks < 4; ks++) {
                uint32_t af[2][4];
                #pragma unroll
                for (int mt = 0; mt < 2; mt++) {
                    af[mt][0] = packh2(sf[mt][2 * ks][0],     sf[mt][2 * ks][1]);
                    af[mt][1] = packh2(sf[mt][2 * ks][2],     sf[mt][2 * ks][3]);
                    af[mt][2] = packh2(sf[mt][2 * ks + 1][0], sf[mt][2 * ks + 1][1]);
                    af[mt][3] = packh2(sf[mt][2 * ks + 1][2], sf[mt][2 * ks + 1][3]);
                }
                #pragma unroll
                for (int p = 0; p < 4; p++) {
                    uint32_t vb[4];
                    ldm_x4t(vb, vfrag_base + (uint32_t)(st * FKV_H * 2)
                                + (uint32_t)((ks * 16 * FQSTR + p * 16) << 1));
                    #pragma unroll
                    for (int mt = 0; mt < 2; mt++) {
                        mma16(acc[mt][2 * p],     af[mt], vb);
                        mma16(acc[mt][2 * p + 1], af[mt], vb + 2);
                    }
                }
            }
        }
    }

    #pragma unroll
    for (int mt = 0; mt < 2; mt++) {
        float inv0 = 1.f / l0[mt], inv1 = 1.f / l1[mt];
        size_t r0 = ((size_t)(b * SS + q0 + qb + mt * 16 + g)) * DD + h * DHD;
        size_t r1 = r0 + 8 * DD;
        #pragma unroll
        for (int nt = 0; nt < 8; nt++) {
            int col = nt * 8 + 2 * c;
            *(__half2*)(O + r0 + col) =
                __floats2half2_rn(acc[mt][nt][0] * inv0, acc[mt][nt][1] * inv0);
            *(__half2*)(O + r1 + col) =
                __floats2half2_rn(acc[mt][nt][2] * inv1, acc[mt][nt][3] * inv1);
        }
    }
}

// ---------------- launch ---------------------------------------------------
extern "C" void kernel_launch(void* const* d_in, const int* in_sizes, int n_in,
                              void* d_out, int out_size)
{
    const float* hidden = (const float*)d_in[0];
    const int*   mask   = (const int*)d_in[1];
    const float* wq = (const float*)d_in[2];
    const float* bq = (const float*)d_in[3];
    const float* wk = (const float*)d_in[4];
    const float* bk = (const float*)d_in[5];
    const float* wv = (const float*)d_in[6];
    const float* bv = (const float*)d_in[7];
    const float* wo = (const float*)d_in[8];
    const float* bo = (const float*)d_in[9];
    const float* w1 = (const float*)d_in[10];
    const float* b1 = (const float*)d_in[11];
    const float* w2 = (const float*)d_in[12];
    const float* b2 = (const float*)d_in[13];
    const float* ln1_g = (const float*)d_in[14];
    const float* ln1_b = (const float*)d_in[15];
    const float* ln2_g = (const float*)d_in[16];
    const float* ln2_b = (const float*)d_in[17];
    float* out = (float*)d_out;

    __half *ln, *qkv, *attn, *f1, *wqkvh, *woh, *w1h, *w2h;
    float *h1, *bqkv;
    cudaGetSymbolAddress((void**)&ln,    g_ln);
    cudaGetSymbolAddress((void**)&qkv,   g_qkv);
    cudaGetSymbolAddress((void**)&attn,  g_attn);
    cudaGetSymbolAddress((void**)&h1,    g_h1);
    cudaGetSymbolAddress((void**)&f1,    g_f1);
    cudaGetSymbolAddress((void**)&wqkvh, g_wqkv);
    cudaGetSymbolAddress((void**)&bqkv,  g_bqkv);
    cudaGetSymbolAddress((void**)&woh,   g_wo);
    cudaGetSymbolAddress((void**)&w1h,   g_w1);
    cudaGetSymbolAddress((void**)&w2h,   g_w2);

    cudaFuncSetAttribute(flash_f16,
                         cudaFuncAttributeMaxDynamicSharedMemorySize, FLASH_SMEM);
    cudaFuncSetAttribute(gemm_f16<1>,
                         cudaFuncAttributeMaxDynamicSharedMemorySize, GEMM_SMEM);
    cudaFuncSetAttribute(gemm_f16<2>,
                         cudaFuncAttributeMaxDynamicSharedMemorySize, GEMM_SMEM);
    cudaFuncSetAttribute(gemm_f16<3>,
                         cudaFuncAttributeMaxDynamicSharedMemorySize, GEMM_SMEM);

    // one fused pack launch (8 float4 in flight per thread)
    pack_all<<<(unsigned)PACK_BLOCKS, 256>>>(wq, wk, wv, wo, w1, w2, bq, bk, bv,
                                             wqkvh, woh, w1h, w2h, bqkv);

    // 1) LN1 (warp-per-row)
    ln_kernel<<<NROWS / 8, 256>>>(hidden, ln1_g, ln1_b, ln);

    // 2) fused QKV projection -> fp16
    dim3 gQKV(NQKV / 128, NROWS / 128);
    gemm_f16<3><<<gQKV, 128, GEMM_SMEM>>>(ln, wqkvh, bqkv, nullptr, qkv,
                                          NROWS, DD, NQKV);

    // 3) attention
    flash_f16<<<dim3(SS / 128, HH, BB), 128, FLASH_SMEM>>>(
        qkv, qkv + DD, qkv + 2 * DD, NQKV, mask, attn);

    // 4) output projection + residual -> fp32
    dim3 gD(DD / 128, NROWS / 128);
    gemm_f16<2><<<gD, 128, GEMM_SMEM>>>(attn, woh, bo, hidden, h1, NROWS, DD, DD);

    // 5) LN2
    ln_kernel<<<NROWS / 8, 256>>>(h1, ln2_g, ln2_b, ln);

    // 6) FFN
    dim3 gF(DFF / 128, NROWS / 128);
    gemm_f16<1><<<gF, 128, GEMM_SMEM>>>(ln, w1h, b1, nullptr, f1, NROWS, DD, DFF);
    gemm_f16<2><<<gD, 128, GEMM_SMEM>>>(f1, w2h, b2, h1, out, NROWS, DFF, DD);
}

// round 14
// speedup vs baseline: 1.1496x; 1.0261x over previous
#include <cuda_runtime.h>
#include <cuda_fp16.h>
#include <math.h>
#include <stdint.h>

#define BB 2
#define SS 2048
#define DD 1024
#define HH 16
#define DHD 64
#define DFF 4096
#define NROWS (BB * SS)
#define NQKV 3072

// ---------------- scratch (device globals; no allocation) ----------------
__device__ __half g_ln[NROWS * DD];
__device__ __half g_qkv[NROWS * NQKV];
__device__ __half g_attn[NROWS * DD];
__device__ float  g_h1[NROWS * DD];
__device__ __half g_f1[NROWS * DFF];
__device__ __half g_wqkv[DD * NQKV];
__device__ float  g_bqkv[NQKV];
__device__ __half g_wo[DD * DD];
__device__ __half g_w1[DD * DFF];
__device__ __half g_w2[DFF * DD];

// ---------------- helpers --------------------------------------------------
__device__ __forceinline__ uint32_t smem_u32(const void* p) {
    uint32_t a;
    asm("{ .reg .u64 t; cvta.to.shared.u64 t, %1; cvt.u32.u64 %0, t; }" : "=r"(a) : "l"(p));
    return a;
}
__device__ __forceinline__ void cp16(void* dst_smem, const void* src) {
    uint32_t d;
    asm("{ .reg .u64 t; cvta.to.shared.u64 t, %1; cvt.u32.u64 %0, t; }"
        : "=r"(d) : "l"(dst_smem));
    asm volatile("cp.async.cg.shared.global [%0], [%1], 16;" :: "r"(d), "l"(src));
}
__device__ __forceinline__ void cp_commit() {
    asm volatile("cp.async.commit_group;");
}
template <int N>
__device__ __forceinline__ void cp_wait() {
    asm volatile("cp.async.wait_group %0;" :: "n"(N));
}
__device__ __forceinline__ void ldm_x4(uint32_t r[4], uint32_t addr) {
    asm volatile("ldmatrix.sync.aligned.m8n8.x4.shared.b16 {%0,%1,%2,%3}, [%4];"
        : "=r"(r[0]), "=r"(r[1]), "=r"(r[2]), "=r"(r[3]) : "r"(addr));
}
__device__ __forceinline__ void ldm_x4t(uint32_t r[4], uint32_t addr) {
    asm volatile("ldmatrix.sync.aligned.m8n8.x4.trans.shared.b16 {%0,%1,%2,%3}, [%4];"
        : "=r"(r[0]), "=r"(r[1]), "=r"(r[2]), "=r"(r[3]) : "r"(addr));
}
__device__ __forceinline__ void mma16(float c[4], const uint32_t a[4], const uint32_t b[2]) {
    asm volatile(
        "mma.sync.aligned.m16n8k16.row.col.f32.f16.f16.f32 "
        "{%0,%1,%2,%3}, {%4,%5,%6,%7}, {%8,%9}, {%0,%1,%2,%3};"
        : "+f"(c[0]), "+f"(c[1]), "+f"(c[2]), "+f"(c[3])
        : "r"(a[0]), "r"(a[1]), "r"(a[2]), "r"(a[3]), "r"(b[0]), "r"(b[1]));
}
__device__ __forceinline__ float ex2f(float x) {
    float r;
    asm("ex2.approx.f32 %0, %1;" : "=f"(r) : "f"(x));
    return r;
}
// packed exp2 of (a, b) in fp16x2; returns bit-pattern usable as mma fragment
__device__ __forceinline__ uint32_t h2exp2_u(float a, float b) {
    __half2 h = __floats2half2_rn(a, b);
    uint32_t x = *(uint32_t*)&h, r;
    asm("ex2.approx.f16x2 %0, %1;" : "=r"(r) : "r"(x));
    return r;
}
__device__ __forceinline__ float gelu_tanh_f(float h) {
    const float c = 0.7978845608028654f;
    float u = c * (h + 0.044715f * h * h * h);
    return 0.5f * h * (1.0f + tanhf(u));
}

// ---------------- ONE fused pack kernel, 8 float4 in flight per thread -----
#define NW (DD * DD / 4)
#define NF (DD * DFF / 4)
#define PACK_TOT (4L * NW + 2L * NF + 768)
#define PACK_BLOCKS ((PACK_TOT + 2047) / 2048)
__global__ void __launch_bounds__(256) pack_all(
    const float* __restrict__ wq, const float* __restrict__ wk,
    const float* __restrict__ wv, const float* __restrict__ wo,
    const float* __restrict__ w1, const float* __restrict__ w2,
    const float* __restrict__ bq, const float* __restrict__ bk,
    const float* __restrict__ bv,
    __half* __restrict__ wqkv, __half* __restrict__ woh,
    __half* __restrict__ w1h, __half* __restrict__ w2h,
    float* __restrict__ bqkv)
{
    #pragma unroll
    for (int j = 0; j < 8; j++) {
        long i = (long)blockIdx.x * 2048 + j * 256 + threadIdx.x;
        if (i >= PACK_TOT) break;
        if (i < 3L * NW) {
            const float* src = (i < NW) ? wq : (i < 2L * NW) ? wk : wv;
            int coff = (i < NW) ? 0 : (i < 2L * NW) ? DD : 2 * DD;
            long ii = i % NW;
            int row = (int)(ii >> 8), c4 = ((int)ii & 255) << 2;
            float4 v = ((const float4*)src)[ii];
            __half2* o = (__half2*)(wqkv + (size_t)row * NQKV + coff + c4);
            o[0] = __floats2half2_rn(v.x, v.y);
            o[1] = __floats2half2_rn(v.z, v.w);
        } else if (i < 4L * NW) {
            long ii = i - 3L * NW;
            float4 v = ((const float4*)wo)[ii];
            __half2* o = (__half2*)(woh + ii * 4);
            o[0] = __floats2half2_rn(v.x, v.y);
            o[1] = __floats2half2_rn(v.z, v.w);
        } else if (i < 4L * NW + NF) {
            long ii = i - 4L * NW;
            float4 v = ((const float4*)w1)[ii];
            __half2* o = (__half2*)(w1h + ii * 4);
            o[0] = __floats2half2_rn(v.x, v.y);
            o[1] = __floats2half2_rn(v.z, v.w);
        } else if (i < 4L * NW + 2L * NF) {
            long ii = i - 4L * NW - NF;
            float4 v = ((const float4*)w2)[ii];
            __half2* o = (__half2*)(w2h + ii * 4);
            o[0] = __floats2half2_rn(v.x, v.y);
            o[1] = __floats2half2_rn(v.z, v.w);
        } else {
            long ii = i - 4L * NW - 2L * NF;   // 0..767
            int jj = (int)ii * 4;
            const float* src = (jj < DD) ? bq : (jj < 2 * DD) ? bk : bv;
            *(float4*)(bqkv + jj) = *(const float4*)(src + (jj & (DD - 1)));
        }
    }
}

// ---------------- LayerNorm: one warp per row, shfl-only -------------------
__global__ void __launch_bounds__(256) ln_kernel(
    const float* __restrict__ x, const float* __restrict__ gw,
    const float* __restrict__ bw, __half* __restrict__ y)
{
    int warp = threadIdx.x >> 5, lane = threadIdx.x & 31;
    int row = blockIdx.x * 8 + warp;
    const float4* xr = (const float4*)(x + (size_t)row * DD);

    float4 v[8];
    float s = 0.f, ss = 0.f;
    #pragma unroll
    for (int i = 0; i < 8; i++) {
        v[i] = xr[lane + i * 32];
        s  += v[i].x + v[i].y + v[i].z + v[i].w;
        ss += v[i].x * v[i].x + v[i].y * v[i].y + v[i].z * v[i].z + v[i].w * v[i].w;
    }
    #pragma unroll
    for (int o = 16; o; o >>= 1) {
        s  += __shfl_xor_sync(0xffffffffu, s,  o);
        ss += __shfl_xor_sync(0xffffffffu, ss, o);
    }
    float mean = s * (1.0f / DD);
    float var  = (ss - s * s * (1.0f / DD)) * (1.0f / (DD - 1));
    var = fmaxf(var, 0.f);
    float rd = 1.0f / (sqrtf(var) + 1e-6f);

    __half2* yo = (__half2*)(y + (size_t)row * DD);
    #pragma unroll
    for (int i = 0; i < 8; i++) {
        float4 g4 = ((const float4*)gw)[lane + i * 32];
        float4 b4 = ((const float4*)bw)[lane + i * 32];
        yo[2 * (lane + i * 32)] =
            __floats2half2_rn(g4.x * (v[i].x - mean) * rd + b4.x,
                              g4.y * (v[i].y - mean) * rd + b4.y);
        yo[2 * (lane + i * 32) + 1] =
            __floats2half2_rn(g4.z * (v[i].z - mean) * rd + b4.z,
                              g4.w * (v[i].w - mean) * rd + b4.w);
    }
}

// ---------------- fp16 mma GEMM (128x128x32, 4 warps x 64x64, 2 CTA/SM) ----
#define TKH 32
#define ASTRH 40
#define BSTRH 136
#define A_TILE_H (128 * ASTRH)
#define B_TILE_H (TKH * BSTRH)
#define STAGE_H (A_TILE_H + B_TILE_H)
#define NSTG 4
#define GEMM_SMEM (NSTG * STAGE_H * 2)

// EPI: 1 = bias+gelu -> fp16 out, 2 = bias+residual -> fp32 out,
//      3 = bias -> fp16 out
template <int EPI>
__global__ void __launch_bounds__(128, 2) gemm_f16(
    const __half* __restrict__ A, const __half* __restrict__ W,
    const float* __restrict__ bias, const float* __restrict__ R,
    void* __restrict__ Cv, int M, int K, int N)
{
    extern __shared__ __half smh[];
    uint32_t sbase = smem_u32(smh);
    int t = threadIdx.x;
    int m0 = blockIdx.y * 128, n0 = blockIdx.x * 128;
    int nkt = K >> 5;

    auto load_tile = [&](int stg, int kt) {
        __half* As = smh + stg * STAGE_H;
        __half* Bs = As + A_TILE_H;
        int k0 = kt * TKH;
        #pragma unroll
        for (int i = 0; i < 4; i++) {
            int id = t + i * 128;
            int row = id >> 2, c8 = (id & 3) << 3;
            cp16(As + row * ASTRH + c8, A + (size_t)(m0 + row) * K + k0 + c8);
        }
        #pragma unroll
        for (int i = 0; i < 4; i++) {
            int id = t + i * 128;
            int row = id >> 4, c8 = (id & 15) << 3;
            cp16(Bs + row * BSTRH + c8, W + (size_t)(k0 + row) * N + n0 + c8);
        }
    };

    float acc[4][8][4];
    #pragma unroll
    for (int mt = 0; mt < 4; mt++)
        #pragma unroll
        for (int nt = 0; nt < 8; nt++)
            #pragma unroll
            for (int i = 0; i < 4; i++) acc[mt][nt][i] = 0.f;

    int lane = t & 31, wid = t >> 5;
    int warpM = wid >> 1, warpN = wid & 1;
    int g = lane >> 2, c = lane & 3;
    int arow_l = lane & 15;
    int acol_l = (lane >> 4) << 3;
    int mat = lane >> 3, lr = lane & 7;
    int bko = ((mat & 1) << 3) + lr;
    int bno = (mat >> 1) << 3;

    #pragma unroll
    for (int s = 0; s < NSTG - 1; s++) { load_tile(s, s); cp_commit(); }

    for (int kt = 0; kt < nkt; kt++) {
        cp_wait<NSTG - 2>();
        __syncthreads();

        int nx = kt + NSTG - 1;
        if (nx < nkt) load_tile(nx & (NSTG - 1), nx);
        cp_commit();

        uint32_t As_u = sbase + (uint32_t)((kt & (NSTG - 1)) * STAGE_H) * 2;
        uint32_t Bs_u = As_u + A_TILE_H * 2;

        // prefetch all fragments for both ks-groups, then mma bursts
        uint32_t af[2][4][4], b4[2][4][4];
        #pragma unroll
        for (int ks = 0; ks < 2; ks++) {
            #pragma unroll
            for (int mt = 0; mt < 4; mt++)
                ldm_x4(af[ks][mt], As_u +
                    ((uint32_t)((warpM * 64 + mt * 16 + arow_l) * ASTRH
                                + ks * 16 + acol_l) << 1));
            #pragma unroll
            for (int p = 0; p < 4; p++) {
                int bk = ks * 16 + bko;
                int bn = warpN * 64 + p * 16 + bno;
                ldm_x4t(b4[ks][p], Bs_u + ((uint32_t)(bk * BSTRH + bn) << 1));
            }
        }
        #pragma unroll
        for (int ks = 0; ks < 2; ks++)
            #pragma unroll
            for (int mt = 0; mt < 4; mt++)
                #pragma unroll
                for (int nt = 0; nt < 8; nt++)
                    mma16(acc[mt][nt], af[ks][mt], &b4[ks][nt >> 1][(nt & 1) << 1]);
    }

    int rbase = m0 + warpM * 64 + g;
    int cbase = n0 + warpN * 64 + 2 * c;

    #pragma unroll
    for (int nt = 0; nt < 8; nt++) {
        int col = cbase + nt * 8;
        float2 b2 = *(const float2*)(bias + col);
        #pragma unroll
        for (int mt = 0; mt < 4; mt++) {
            int r0 = rbase + mt * 16;
            float v0x = acc[mt][nt][0] + b2.x;
            float v0y = acc[mt][nt][1] + b2.y;
            float v1x = acc[mt][nt][2] + b2.x;
            float v1y = acc[mt][nt][3] + b2.y;
            if (EPI == 2) {
                float* C = (float*)Cv;
                float2 r0v = *(const float2*)(R + (size_t)r0 * N + col);
                float2 r1v = *(const float2*)(R + (size_t)(r0 + 8) * N + col);
                *(float2*)(C + (size_t)r0 * N + col) =
                    make_float2(v0x + r0v.x, v0y + r0v.y);
                *(float2*)(C + (size_t)(r0 + 8) * N + col) =
                    make_float2(v1x + r1v.x, v1y + r1v.y);
            } else {
                if (EPI == 1) {
                    v0x = gelu_tanh_f(v0x); v0y = gelu_tanh_f(v0y);
                    v1x = gelu_tanh_f(v1x); v1y = gelu_tanh_f(v1y);
                }
                __half* C = (__half*)Cv;
                *(__half2*)(C + (size_t)r0 * N + col) = __floats2half2_rn(v0x, v0y);
                *(__half2*)(C + (size_t)(r0 + 8) * N + col) = __floats2half2_rn(v1x, v1y);
            }
        }
    }
}

// ---------------- fp16 tensor-core flash attention ---------------------------
// 4 warps x 32 q-rows, 4-stage KV pipeline, fp16x2 exponentials whose outputs
// feed the PV mma directly (no re-pack).
#define FQSTR 72
#define FQ_H (128 * FQSTR)
#define FKV_H (64 * FQSTR)
#define KOFF FQ_H
#define VOFF (FQ_H + 4 * FKV_H)
#define MOFF_BYTES ((FQ_H + 8 * FKV_H) * 2)
#define FLASH_SMEM (MOFF_BYTES + 4 * 64 * 4 + 16)
#define QSCALE 0.1803368801111204f   /* 0.125 * log2(e) */
#define MBIAS  (-1.44269504e9f)      /* -1e9 * log2(e)  */

__global__ void __launch_bounds__(128, 2) flash_f16(
    const __half* __restrict__ Q, const __half* __restrict__ Kg,
    const __half* __restrict__ Vg, int ldq, const int* __restrict__ mask,
    __half* __restrict__ O)
{
    extern __shared__ __half smh[];
    uint32_t sbase = smem_u32(smh);
    int* mksm = (int*)((char*)smh + MOFF_BYTES);
    int t = threadIdx.x;
    int lane = t & 31, wid = t >> 5;
    int g = lane >> 2, c = lane & 3;
    int q0 = blockIdx.x * 128;
    int h = blockIdx.y, b = blockIdx.z;
    size_t baseQ = ((size_t)(b * SS + q0)) * ldq + h * DHD;

    auto load_kv = [&](int kt, int s) {
        size_t baseK = ((size_t)(b * SS + kt * 64)) * ldq + h * DHD;
        __half* Kb = smh + KOFF + s * FKV_H;
        __half* Vb = smh + VOFF + s * FKV_H;
        #pragma unroll
        for (int i = 0; i < 4; i++) {
            int id = t + i * 128;
            int row = id >> 3, c8 = (id & 7) << 3;
            cp16(Kb + row * FQSTR + c8, Kg + baseK + (size_t)row * ldq + c8);
            cp16(Vb + row * FQSTR + c8, Vg + baseK + (size_t)row * ldq + c8);
        }
        if (t < 16) cp16(mksm + s * 64 + t * 4, mask + b * SS + kt * 64 + t * 4);
    };

    load_kv(0, 0);
    #pragma unroll
    for (int i = 0; i < 8; i++) {
        int id = t + i * 128;
        int row = id >> 3, c8 = (id & 7) << 3;
        cp16(smh + row * FQSTR + c8, Q + baseQ + (size_t)row * ldq + c8);
    }
    cp_commit();
    load_kv(1, 1);
    cp_commit();
    load_kv(2, 2);
    cp_commit();

    cp_wait<2>();
    __syncthreads();

    int arow_l = lane & 15;
    int acol_l = (lane >> 4) << 3;
    int mat = lane >> 3, lr = lane & 7;
    uint32_t qf[2][4][4];
    int qb = wid * 32;
    {
        __half2 qs = __float2half2_rn(QSCALE);
        #pragma unroll
        for (int mt = 0; mt < 2; mt++)
            #pragma unroll
            for (int ks = 0; ks < 4; ks++) {
                ldm_x4(qf[mt][ks], sbase +
                    ((uint32_t)((qb + mt * 16 + arow_l) * FQSTR
                                + ks * 16 + acol_l) << 1));
                #pragma unroll
                for (int i = 0; i < 4; i++) {
                    __half2 hv = *(__half2*)&qf[mt][ks][i];
                    hv = __hmul2(hv, qs);
                    qf[mt][ks][i] = *(uint32_t*)&hv;
                }
            }
    }

    float m0[2], m1[2], l0[2], l1[2];
    #pragma unroll
    for (int mt = 0; mt < 2; mt++) {
        m0[mt] = -1e30f; m1[mt] = -1e30f; l0[mt] = 0.f; l1[mt] = 0.f;
    }
    float acc[2][8][4];
    #pragma unroll
    for (int mt = 0; mt < 2; mt++)
        #pragma unroll
        for (int nt = 0; nt < 8; nt++)
            #pragma unroll
            for (int i = 0; i < 4; i++) acc[mt][nt][i] = 0.f;

    uint32_t kfrag_base = sbase + ((uint32_t)(((mat >> 1) << 3) + lr) * FQSTR
                                   + ((mat & 1) << 3)) * 2 + KOFF * 2;
    uint32_t vfrag_base = sbase + ((uint32_t)((((mat & 1) << 3) + lr) * FQSTR)
                                   + (((mat >> 1) << 3))) * 2 + VOFF * 2;

    for (int kto = 0; kto < SS / 64; kto += 4) {
        #pragma unroll
        for (int st = 0; st < 4; st++) {
            int kt = kto + st;
            cp_wait<2>();
            __syncthreads();

            int nx = kt + 3;
            if (nx < SS / 64) load_kv(nx, nx & 3);
            cp_commit();

            const int* mk = mksm + st * 64;

            float sf[2][8][4];
            #pragma unroll
            for (int mt = 0; mt < 2; mt++)
                #pragma unroll
                for (int nt = 0; nt < 8; nt++)
                    #pragma unroll
                    for (int i = 0; i < 4; i++) sf[mt][nt][i] = 0.f;

            #pragma unroll
            for (int ks = 0; ks < 4; ks++) {
                #pragma unroll
                for (int p = 0; p < 4; p++) {
                    uint32_t kb[4];
                    ldm_x4(kb, kfrag_base + (uint32_t)(st * FKV_H * 2)
                               + (uint32_t)((p * 16 * FQSTR + ks * 16) << 1));
                    #pragma unroll
                    for (int mt = 0; mt < 2; mt++) {
                        mma16(sf[mt][2 * p],     qf[mt][ks], kb);
                        mma16(sf[mt][2 * p + 1], qf[mt][ks], kb + 2);
                    }
                }
            }

            // softmax: fp32 max bookkeeping, fp16x2 exponentials (P = mma frags)
            uint32_t ph[2][8][2];
            #pragma unroll
            for (int mt = 0; mt < 2; mt++) {
                float mx0 = -1e30f, mx1 = -1e30f;
                #pragma unroll
                for (int nt = 0; nt < 8; nt++) {
                    float bia0 = mk[nt * 8 + 2 * c]     ? 0.f : MBIAS;
                    float bia1 = mk[nt * 8 + 2 * c + 1] ? 0.f : MBIAS;
                    sf[mt][nt][0] += bia0; sf[mt][nt][1] += bia1;
                    sf[mt][nt][2] += bia0; sf[mt][nt][3] += bia1;
                    mx0 = fmaxf(mx0, fmaxf(sf[mt][nt][0], sf[mt][nt][1]));
                    mx1 = fmaxf(mx1, fmaxf(sf[mt][nt][2], sf[mt][nt][3]));
                }
                mx0 = fmaxf(mx0, __shfl_xor_sync(0xffffffffu, mx0, 1));
                mx0 = fmaxf(mx0, __shfl_xor_sync(0xffffffffu, mx0, 2));
                mx1 = fmaxf(mx1, __shfl_xor_sync(0xffffffffu, mx1, 1));
                mx1 = fmaxf(mx1, __shfl_xor_sync(0xffffffffu, mx1, 2));

                float mn0 = fmaxf(m0[mt], mx0), mn1 = fmaxf(m1[mt], mx1);
                float al0 = ex2f(m0[mt] - mn0), al1 = ex2f(m1[mt] - mn1);
                m0[mt] = mn0; m1[mt] = mn1;

                __half2 hs0 = __float2half2_rn(0.f), hs1 = hs0;
                #pragma unroll
                for (int nt = 0; nt < 8; nt++) {
                    uint32_t e0 = h2exp2_u(sf[mt][nt][0] - mn0, sf[mt][nt][1] - mn0);
                    uint32_t e1 = h2exp2_u(sf[mt][nt][2] - mn1, sf[mt][nt][3] - mn1);
                    ph[mt][nt][0] = e0;
                    ph[mt][nt][1] = e1;
                    hs0 = __hadd2(hs0, *(__half2*)&e0);
                    hs1 = __hadd2(hs1, *(__half2*)&e1);
                }
                float ps0 = __low2float(hs0) + __high2float(hs0);
                float ps1 = __low2float(hs1) + __high2float(hs1);
                ps0 += __shfl_xor_sync(0xffffffffu, ps0, 1);
                ps0 += __shfl_xor_sync(0xffffffffu, ps0, 2);
                ps1 += __shfl_xor_sync(0xffffffffu, ps1, 1);
                ps1 += __shfl_xor_sync(0xffffffffu, ps1, 2);
                l0[mt] = l0[mt] * al0 + ps0;
                l1[mt] = l1[mt] * al1 + ps1;

                #pragma unroll
                for (int nt = 0; nt < 8; nt++) {
                    acc[mt][nt][0] *= al0; acc[mt][nt][1] *= al0;
                    acc[mt][nt][2] *= al1; acc[mt][nt][3] *= al1;
                }
            }

            // acc += P V : P fragments come straight from the fp16x2 exps
            #pragma unroll
            for (int ks = 0; ks < 4; ks++) {
                #pragma unroll
                for (int p = 0; p < 4; p++) {
                    uint32_t vb[4];
                    ldm_x4t(vb, vfrag_base + (uint32_t)(st * FKV_H * 2)
                                + (uint32_t)((ks * 16 * FQSTR + p * 16) << 1));
                    #pragma unroll
                    for (int mt = 0; mt < 2; mt++) {
                        uint32_t af[4];
                        af[0] = ph[mt][2 * ks][0];
                        af[1] = ph[mt][2 * ks][1];
                        af[2] = ph[mt][2 * ks + 1][0];
                        af[3] = ph[mt][2 * ks + 1][1];
                        mma16(acc[mt][2 * p],     af, vb);
                        mma16(acc[mt][2 * p + 1], af, vb + 2);
                    }
                }
            }
        }
    }

    #pragma unroll
    for (int mt = 0; mt < 2; mt++) {
        float inv0 = 1.f / l0[mt], inv1 = 1.f / l1[mt];
        size_t r0 = ((size_t)(b * SS + q0 + qb + mt * 16 + g)) * DD + h * DHD;
        size_t r1 = r0 + 8 * DD;
        #pragma unroll
        for (int nt = 0; nt < 8; nt++) {
            int col = nt * 8 + 2 * c;
            *(__half2*)(O + r0 + col) =
                __floats2half2_rn(acc[mt][nt][0] * inv0, acc[mt][nt][1] * inv0);
            *(__half2*)(O + r1 + col) =
                __floats2half2_rn(acc[mt][nt][2] * inv1, acc[mt][nt][3] * inv1);
        }
    }
}

// ---------------- launch ---------------------------------------------------
extern "C" void kernel_launch(void* const* d_in, const int* in_sizes, int n_in,
                              void* d_out, int out_size)
{
    const float* hidden = (const float*)d_in[0];
    const int*   mask   = (const int*)d_in[1];
    const float* wq = (const float*)d_in[2];
    const float* bq = (const float*)d_in[3];
    const float* wk = (const float*)d_in[4];
    const float* bk = (const float*)d_in[5];
    const float* wv = (const float*)d_in[6];
    const float* bv = (const float*)d_in[7];
    const float* wo = (const float*)d_in[8];
    const float* bo = (const float*)d_in[9];
    const float* w1 = (const float*)d_in[10];
    const float* b1 = (const float*)d_in[11];
    const float* w2 = (const float*)d_in[12];
    const float* b2 = (const float*)d_in[13];
    const float* ln1_g = (const float*)d_in[14];
    const float* ln1_b = (const float*)d_in[15];
    const float* ln2_g = (const float*)d_in[16];
    const float* ln2_b = (const float*)d_in[17];
    float* out = (float*)d_out;

    __half *ln, *qkv, *attn, *f1, *wqkvh, *woh, *w1h, *w2h;
    float *h1, *bqkv;
    cudaGetSymbolAddress((void**)&ln,    g_ln);
    cudaGetSymbolAddress((void**)&qkv,   g_qkv);
    cudaGetSymbolAddress((void**)&attn,  g_attn);
    cudaGetSymbolAddress((void**)&h1,    g_h1);
    cudaGetSymbolAddress((void**)&f1,    g_f1);
    cudaGetSymbolAddress((void**)&wqkvh, g_wqkv);
    cudaGetSymbolAddress((void**)&bqkv,  g_bqkv);
    cudaGetSymbolAddress((void**)&woh,   g_wo);
    cudaGetSymbolAddress((void**)&w1h,   g_w1);
    cudaGetSymbolAddress((void**)&w2h,   g_w2);

    cudaFuncSetAttribute(flash_f16,
                         cudaFuncAttributeMaxDynamicSharedMemorySize, FLASH_SMEM);
    cudaFuncSetAttribute(gemm_f16<1>,
                         cudaFuncAttributeMaxDynamicSharedMemorySize, GEMM_SMEM);
    cudaFuncSetAttribute(gemm_f16<2>,
                         cudaFuncAttributeMaxDynamicSharedMemorySize, GEMM_SMEM);
    cudaFuncSetAttribute(gemm_f16<3>,
                         cudaFuncAttributeMaxDynamicSharedMemorySize, GEMM_SMEM);

    // one fused pack launch
    pack_all<<<(unsigned)PACK_BLOCKS, 256>>>(wq, wk, wv, wo, w1, w2, bq, bk, bv,
                                             wqkvh, woh, w1h, w2h, bqkv);

    // 1) LN1 (warp-per-row)
    ln_kernel<<<NROWS / 8, 256>>>(hidden, ln1_g, ln1_b, ln);

    // 2) fused QKV projection -> fp16
    dim3 gQKV(NQKV / 128, NROWS / 128);
    gemm_f16<3><<<gQKV, 128, GEMM_SMEM>>>(ln, wqkvh, bqkv, nullptr, qkv,
                                          NROWS, DD, NQKV);

    // 3) attention
    flash_f16<<<dim3(SS / 128, HH, BB), 128, FLASH_SMEM>>>(
        qkv, qkv + DD, qkv + 2 * DD, NQKV, mask, attn);

    // 4) output projection + residual -> fp32
    dim3 gD(DD / 128, NROWS / 128);
    gemm_f16<2><<<gD, 128, GEMM_SMEM>>>(attn, woh, bo, hidden, h1, NROWS, DD, DD);

    // 5) LN2
    ln_kernel<<<NROWS / 8, 256>>>(h1, ln2_g, ln2_b, ln);

    // 6) FFN
    dim3 gF(DFF / 128, NROWS / 128);
    gemm_f16<1><<<gF, 128, GEMM_SMEM>>>(ln, w1h, b1, nullptr, f1, NROWS, DD, DFF);
    gemm_f16<2><<<gD, 128, GEMM_SMEM>>>(f1, w2h, b2, h1, out, NROWS, DFF, DD);
}

// round 15
// speedup vs baseline: 1.1602x; 1.0093x over previous
#include <cuda_runtime.h>
#include <cuda_fp16.h>
#include <math.h>
#include <stdint.h>

#define BB 2
#define SS 2048
#define DD 1024
#define HH 16
#define DHD 64
#define DFF 4096
#define NROWS (BB * SS)
#define NQKV 3072

// ---------------- scratch (device globals; no allocation) ----------------
__device__ __half g_ln[NROWS * DD];
__device__ __half g_qkv[NROWS * NQKV];
__device__ __half g_attn[NROWS * DD];
__device__ float  g_h1[NROWS * DD];
__device__ __half g_f1[NROWS * DFF];
__device__ __half g_wqkv[DD * NQKV];
__device__ float  g_bqkv[NQKV];
__device__ __half g_wo[DD * DD];
__device__ __half g_w1[DD * DFF];
__device__ __half g_w2[DFF * DD];

// ---------------- helpers --------------------------------------------------
__device__ __forceinline__ uint32_t smem_u32(const void* p) {
    uint32_t a;
    asm("{ .reg .u64 t; cvta.to.shared.u64 t, %1; cvt.u32.u64 %0, t; }" : "=r"(a) : "l"(p));
    return a;
}
__device__ __forceinline__ void cp16(void* dst_smem, const void* src) {
    uint32_t d;
    asm("{ .reg .u64 t; cvta.to.shared.u64 t, %1; cvt.u32.u64 %0, t; }"
        : "=r"(d) : "l"(dst_smem));
    asm volatile("cp.async.cg.shared.global [%0], [%1], 16;" :: "r"(d), "l"(src));
}
__device__ __forceinline__ void cp_commit() {
    asm volatile("cp.async.commit_group;");
}
template <int N>
__device__ __forceinline__ void cp_wait() {
    asm volatile("cp.async.wait_group %0;" :: "n"(N));
}
__device__ __forceinline__ void ldm_x4(uint32_t r[4], uint32_t addr) {
    asm volatile("ldmatrix.sync.aligned.m8n8.x4.shared.b16 {%0,%1,%2,%3}, [%4];"
        : "=r"(r[0]), "=r"(r[1]), "=r"(r[2]), "=r"(r[3]) : "r"(addr));
}
__device__ __forceinline__ void ldm_x4t(uint32_t r[4], uint32_t addr) {
    asm volatile("ldmatrix.sync.aligned.m8n8.x4.trans.shared.b16 {%0,%1,%2,%3}, [%4];"
        : "=r"(r[0]), "=r"(r[1]), "=r"(r[2]), "=r"(r[3]) : "r"(addr));
}
__device__ __forceinline__ void mma16(float c[4], const uint32_t a[4], const uint32_t b[2]) {
    asm volatile(
        "mma.sync.aligned.m16n8k16.row.col.f32.f16.f16.f32 "
        "{%0,%1,%2,%3}, {%4,%5,%6,%7}, {%8,%9}, {%0,%1,%2,%3};"
        : "+f"(c[0]), "+f"(c[1]), "+f"(c[2]), "+f"(c[3])
        : "r"(a[0]), "r"(a[1]), "r"(a[2]), "r"(a[3]), "r"(b[0]), "r"(b[1]));
}
__device__ __forceinline__ float ex2f(float x) {
    float r;
    asm("ex2.approx.f32 %0, %1;" : "=f"(r) : "f"(x));
    return r;
}
__device__ __forceinline__ uint32_t h2exp2_u(float a, float b) {
    __half2 h = __floats2half2_rn(a, b);
    uint32_t x = *(uint32_t*)&h, r;
    asm("ex2.approx.f16x2 %0, %1;" : "=r"(r) : "r"(x));
    return r;
}
__device__ __forceinline__ float gelu_tanh_f(float h) {
    const float c = 0.7978845608028654f;
    float u = c * (h + 0.044715f * h * h * h);
    return 0.5f * h * (1.0f + tanhf(u));
}

// ---------------- ONE fused pack kernel, 8 float4 in flight per thread -----
#define NW (DD * DD / 4)
#define NF (DD * DFF / 4)
#define PACK_TOT (4L * NW + 2L * NF + 768)
#define PACK_BLOCKS ((PACK_TOT + 2047) / 2048)
__global__ void __launch_bounds__(256) pack_all(
    const float* __restrict__ wq, const float* __restrict__ wk,
    const float* __restrict__ wv, const float* __restrict__ wo,
    const float* __restrict__ w1, const float* __restrict__ w2,
    const float* __restrict__ bq, const float* __restrict__ bk,
    const float* __restrict__ bv,
    __half* __restrict__ wqkv, __half* __restrict__ woh,
    __half* __restrict__ w1h, __half* __restrict__ w2h,
    float* __restrict__ bqkv)
{
    #pragma unroll
    for (int j = 0; j < 8; j++) {
        long i = (long)blockIdx.x * 2048 + j * 256 + threadIdx.x;
        if (i >= PACK_TOT) break;
        if (i < 3L * NW) {
            const float* src = (i < NW) ? wq : (i < 2L * NW) ? wk : wv;
            int coff = (i < NW) ? 0 : (i < 2L * NW) ? DD : 2 * DD;
            long ii = i % NW;
            int row = (int)(ii >> 8), c4 = ((int)ii & 255) << 2;
            float4 v = ((const float4*)src)[ii];
            __half2* o = (__half2*)(wqkv + (size_t)row * NQKV + coff + c4);
            o[0] = __floats2half2_rn(v.x, v.y);
            o[1] = __floats2half2_rn(v.z, v.w);
        } else if (i < 4L * NW) {
            long ii = i - 3L * NW;
            float4 v = ((const float4*)wo)[ii];
            __half2* o = (__half2*)(woh + ii * 4);
            o[0] = __floats2half2_rn(v.x, v.y);
            o[1] = __floats2half2_rn(v.z, v.w);
        } else if (i < 4L * NW + NF) {
            long ii = i - 4L * NW;
            float4 v = ((const float4*)w1)[ii];
            __half2* o = (__half2*)(w1h + ii * 4);
            o[0] = __floats2half2_rn(v.x, v.y);
            o[1] = __floats2half2_rn(v.z, v.w);
        } else if (i < 4L * NW + 2L * NF) {
            long ii = i - 4L * NW - NF;
            float4 v = ((const float4*)w2)[ii];
            __half2* o = (__half2*)(w2h + ii * 4);
            o[0] = __floats2half2_rn(v.x, v.y);
            o[1] = __floats2half2_rn(v.z, v.w);
        } else {
            long ii = i - 4L * NW - 2L * NF;   // 0..767
            int jj = (int)ii * 4;
            const float* src = (jj < DD) ? bq : (jj < 2 * DD) ? bk : bv;
            *(float4*)(bqkv + jj) = *(const float4*)(src + (jj & (DD - 1)));
        }
    }
}

// ---------------- LayerNorm: one warp per row, shfl-only -------------------
__global__ void __launch_bounds__(256) ln_kernel(
    const float* __restrict__ x, const float* __restrict__ gw,
    const float* __restrict__ bw, __half* __restrict__ y)
{
    int warp = threadIdx.x >> 5, lane = threadIdx.x & 31;
    int row = blockIdx.x * 8 + warp;
    const float4* xr = (const float4*)(x + (size_t)row * DD);

    float4 v[8];
    float s = 0.f, ss = 0.f;
    #pragma unroll
    for (int i = 0; i < 8; i++) {
        v[i] = xr[lane + i * 32];
        s  += v[i].x + v[i].y + v[i].z + v[i].w;
        ss += v[i].x * v[i].x + v[i].y * v[i].y + v[i].z * v[i].z + v[i].w * v[i].w;
    }
    #pragma unroll
    for (int o = 16; o; o >>= 1) {
        s  += __shfl_xor_sync(0xffffffffu, s,  o);
        ss += __shfl_xor_sync(0xffffffffu, ss, o);
    }
    float mean = s * (1.0f / DD);
    float var  = (ss - s * s * (1.0f / DD)) * (1.0f / (DD - 1));
    var = fmaxf(var, 0.f);
    float rd = 1.0f / (sqrtf(var) + 1e-6f);

    __half2* yo = (__half2*)(y + (size_t)row * DD);
    #pragma unroll
    for (int i = 0; i < 8; i++) {
        float4 g4 = ((const float4*)gw)[lane + i * 32];
        float4 b4 = ((const float4*)bw)[lane + i * 32];
        yo[2 * (lane + i * 32)] =
            __floats2half2_rn(g4.x * (v[i].x - mean) * rd + b4.x,
                              g4.y * (v[i].y - mean) * rd + b4.y);
        yo[2 * (lane + i * 32) + 1] =
            __floats2half2_rn(g4.z * (v[i].z - mean) * rd + b4.z,
                              g4.w * (v[i].w - mean) * rd + b4.w);
    }
}

// ---------------- fp16 mma GEMM (128x128x32, 4 warps x 64x64, 2 CTA/SM) ----
#define TKH 32
#define ASTRH 40
#define BSTRH 136
#define A_TILE_H (128 * ASTRH)
#define B_TILE_H (TKH * BSTRH)
#define STAGE_H (A_TILE_H + B_TILE_H)
#define NSTG 4
#define GEMM_SMEM (NSTG * STAGE_H * 2)

// EPI: 1 = bias+gelu -> fp16 out, 2 = bias+residual -> fp32 out,
//      3 = bias -> fp16 out
template <int EPI>
__global__ void __launch_bounds__(128, 2) gemm_f16(
    const __half* __restrict__ A, const __half* __restrict__ W,
    const float* __restrict__ bias, const float* __restrict__ R,
    void* __restrict__ Cv, int M, int K, int N)
{
    extern __shared__ __half smh[];
    uint32_t sbase = smem_u32(smh);
    int t = threadIdx.x;
    int m0 = blockIdx.y * 128, n0 = blockIdx.x * 128;
    int nkt = K >> 5;

    auto load_tile = [&](int stg, int kt) {
        __half* As = smh + stg * STAGE_H;
        __half* Bs = As + A_TILE_H;
        int k0 = kt * TKH;
        #pragma unroll
        for (int i = 0; i < 4; i++) {
            int id = t + i * 128;
            int row = id >> 2, c8 = (id & 3) << 3;
            cp16(As + row * ASTRH + c8, A + (size_t)(m0 + row) * K + k0 + c8);
        }
        #pragma unroll
        for (int i = 0; i < 4; i++) {
            int id = t + i * 128;
            int row = id >> 4, c8 = (id & 15) << 3;
            cp16(Bs + row * BSTRH + c8, W + (size_t)(k0 + row) * N + n0 + c8);
        }
    };

    float acc[4][8][4];
    #pragma unroll
    for (int mt = 0; mt < 4; mt++)
        #pragma unroll
        for (int nt = 0; nt < 8; nt++)
            #pragma unroll
            for (int i = 0; i < 4; i++) acc[mt][nt][i] = 0.f;

    int lane = t & 31, wid = t >> 5;
    int warpM = wid >> 1, warpN = wid & 1;
    int g = lane >> 2, c = lane & 3;
    int arow_l = lane & 15;
    int acol_l = (lane >> 4) << 3;
    int mat = lane >> 3, lr = lane & 7;
    int bko = ((mat & 1) << 3) + lr;
    int bno = (mat >> 1) << 3;

    #pragma unroll
    for (int s = 0; s < NSTG - 1; s++) { load_tile(s, s); cp_commit(); }

    for (int kt = 0; kt < nkt; kt++) {
        cp_wait<NSTG - 2>();
        __syncthreads();

        int nx = kt + NSTG - 1;
        if (nx < nkt) load_tile(nx & (NSTG - 1), nx);
        cp_commit();

        uint32_t As_u = sbase + (uint32_t)((kt & (NSTG - 1)) * STAGE_H) * 2;
        uint32_t Bs_u = As_u + A_TILE_H * 2;

        uint32_t af[2][4][4], b4[2][4][4];
        #pragma unroll
        for (int ks = 0; ks < 2; ks++) {
            #pragma unroll
            for (int mt = 0; mt < 4; mt++)
                ldm_x4(af[ks][mt], As_u +
                    ((uint32_t)((warpM * 64 + mt * 16 + arow_l) * ASTRH
                                + ks * 16 + acol_l) << 1));
            #pragma unroll
            for (int p = 0; p < 4; p++) {
                int bk = ks * 16 + bko;
                int bn = warpN * 64 + p * 16 + bno;
                ldm_x4t(b4[ks][p], Bs_u + ((uint32_t)(bk * BSTRH + bn) << 1));
            }
        }
        #pragma unroll
        for (int ks = 0; ks < 2; ks++)
            #pragma unroll
            for (int mt = 0; mt < 4; mt++)
                #pragma unroll
                for (int nt = 0; nt < 8; nt++)
                    mma16(acc[mt][nt], af[ks][mt], &b4[ks][nt >> 1][(nt & 1) << 1]);
    }

    int rbase = m0 + warpM * 64 + g;
    int cbase = n0 + warpN * 64 + 2 * c;

    #pragma unroll
    for (int nt = 0; nt < 8; nt++) {
        int col = cbase + nt * 8;
        float2 b2 = *(const float2*)(bias + col);
        #pragma unroll
        for (int mt = 0; mt < 4; mt++) {
            int r0 = rbase + mt * 16;
            float v0x = acc[mt][nt][0] + b2.x;
            float v0y = acc[mt][nt][1] + b2.y;
            float v1x = acc[mt][nt][2] + b2.x;
            float v1y = acc[mt][nt][3] + b2.y;
            if (EPI == 2) {
                float* C = (float*)Cv;
                float2 r0v = *(const float2*)(R + (size_t)r0 * N + col);
                float2 r1v = *(const float2*)(R + (size_t)(r0 + 8) * N + col);
                *(float2*)(C + (size_t)r0 * N + col) =
                    make_float2(v0x + r0v.x, v0y + r0v.y);
                *(float2*)(C + (size_t)(r0 + 8) * N + col) =
                    make_float2(v1x + r1v.x, v1y + r1v.y);
            } else {
                if (EPI == 1) {
                    v0x = gelu_tanh_f(v0x); v0y = gelu_tanh_f(v0y);
                    v1x = gelu_tanh_f(v1x); v1y = gelu_tanh_f(v1y);
                }
                __half* C = (__half*)Cv;
                *(__half2*)(C + (size_t)r0 * N + col) = __floats2half2_rn(v0x, v0y);
                *(__half2*)(C + (size_t)(r0 + 8) * N + col) = __floats2half2_rn(v1x, v1y);
            }
        }
    }
}

// ---------------- fp16 flash attention, softmax/PV software-pipelined -------
// PV of tile t-1 issues between QK(t) and softmax(t), so tensor work covers
// the scalar softmax dependency stall. Prefetch distance kt+2 keeps V(t-1)
// alive (stage (t+3)&3 is never the write target (t+2)&3).
#define FQSTR 72
#define FQ_H (128 * FQSTR)
#define FKV_H (64 * FQSTR)
#define KOFF FQ_H
#define VOFF (FQ_H + 4 * FKV_H)
#define MOFF_BYTES ((FQ_H + 8 * FKV_H) * 2)
#define FLASH_SMEM (MOFF_BYTES + 4 * 64 * 4 + 16)
#define QSCALE 0.1803368801111204f   /* 0.125 * log2(e) */
#define MBIAS  (-1.44269504e9f)      /* -1e9 * log2(e)  */
#define NT_KV (SS / 64)

__global__ void __launch_bounds__(128, 2) flash_f16(
    const __half* __restrict__ Q, const __half* __restrict__ Kg,
    const __half* __restrict__ Vg, int ldq, const int* __restrict__ mask,
    __half* __restrict__ O)
{
    extern __shared__ __half smh[];
    uint32_t sbase = smem_u32(smh);
    int* mksm = (int*)((char*)smh + MOFF_BYTES);
    int t = threadIdx.x;
    int lane = t & 31, wid = t >> 5;
    int g = lane >> 2, c = lane & 3;
    int q0 = blockIdx.x * 128;
    int h = blockIdx.y, b = blockIdx.z;
    size_t baseQ = ((size_t)(b * SS + q0)) * ldq + h * DHD;

    auto load_kv = [&](int kt, int s) {
        size_t baseK = ((size_t)(b * SS + kt * 64)) * ldq + h * DHD;
        __half* Kb = smh + KOFF + s * FKV_H;
        __half* Vb = smh + VOFF + s * FKV_H;
        #pragma unroll
        for (int i = 0; i < 4; i++) {
            int id = t + i * 128;
            int row = id >> 3, c8 = (id & 7) << 3;
            cp16(Kb + row * FQSTR + c8, Kg + baseK + (size_t)row * ldq + c8);
            cp16(Vb + row * FQSTR + c8, Vg + baseK + (size_t)row * ldq + c8);
        }
        if (t < 16) cp16(mksm + s * 64 + t * 4, mask + b * SS + kt * 64 + t * 4);
    };

    // prologue: stages 0 and 1 in flight (loop loads kt+2 starting at kt=0)
    load_kv(0, 0);
    #pragma unroll
    for (int i = 0; i < 8; i++) {
        int id = t + i * 128;
        int row = id >> 3, c8 = (id & 7) << 3;
        cp16(smh + row * FQSTR + c8, Q + baseQ + (size_t)row * ldq + c8);
    }
    cp_commit();
    load_kv(1, 1);
    cp_commit();

    cp_wait<1>();
    __syncthreads();

    int arow_l = lane & 15;
    int acol_l = (lane >> 4) << 3;
    int mat = lane >> 3, lr = lane & 7;
    uint32_t qf[2][4][4];
    int qb = wid * 32;
    {
        __half2 qs = __float2half2_rn(QSCALE);
        #pragma unroll
        for (int mt = 0; mt < 2; mt++)
            #pragma unroll
            for (int ks = 0; ks < 4; ks++) {
                ldm_x4(qf[mt][ks], sbase +
                    ((uint32_t)((qb + mt * 16 + arow_l) * FQSTR
                                + ks * 16 + acol_l) << 1));
                #pragma unroll
                for (int i = 0; i < 4; i++) {
                    __half2 hv = *(__half2*)&qf[mt][ks][i];
                    hv = __hmul2(hv, qs);
                    qf[mt][ks][i] = *(uint32_t*)&hv;
                }
            }
    }

    float m0[2], m1[2], l0[2], l1[2];
    float al0s[2], al1s[2];
    #pragma unroll
    for (int mt = 0; mt < 2; mt++) {
        m0[mt] = -1e30f; m1[mt] = -1e30f; l0[mt] = 0.f; l1[mt] = 0.f;
        al0s[mt] = 1.f; al1s[mt] = 1.f;
    }
    float acc[2][8][4];
    #pragma unroll
    for (int mt = 0; mt < 2; mt++)
        #pragma unroll
        for (int nt = 0; nt < 8; nt++)
            #pragma unroll
            for (int i = 0; i < 4; i++) acc[mt][nt][i] = 0.f;

    uint32_t ph[2][8][2];   // P fragments of the PREVIOUS tile (deferred PV)

    uint32_t kfrag_base = sbase + ((uint32_t)(((mat >> 1) << 3) + lr) * FQSTR
                                   + ((mat & 1) << 3)) * 2 + KOFF * 2;
    uint32_t vfrag_base = sbase + ((uint32_t)((((mat & 1) << 3) + lr) * FQSTR)
                                   + (((mat >> 1) << 3))) * 2 + VOFF * 2;

    for (int kto = 0; kto < NT_KV; kto += 4) {
        #pragma unroll
        for (int st = 0; st < 4; st++) {
            int kt = kto + st;
            cp_wait<1>();
            __syncthreads();

            int nx = kt + 2;
            if (nx < NT_KV) load_kv(nx, nx & 3);
            cp_commit();

            const int* mk = mksm + st * 64;

            // ---- QK mma for tile kt ----
            float sf[2][8][4];
            #pragma unroll
            for (int mt = 0; mt < 2; mt++)
                #pragma unroll
                for (int nt = 0; nt < 8; nt++)
                    #pragma unroll
                    for (int i = 0; i < 4; i++) sf[mt][nt][i] = 0.f;

            #pragma unroll
            for (int ks = 0; ks < 4; ks++) {
                #pragma unroll
                for (int p = 0; p < 4; p++) {
                    uint32_t kb[4];
                    ldm_x4(kb, kfrag_base + (uint32_t)(st * FKV_H * 2)
                               + (uint32_t)((p * 16 * FQSTR + ks * 16) << 1));
                    #pragma unroll
                    for (int mt = 0; mt < 2; mt++) {
                        mma16(sf[mt][2 * p],     qf[mt][ks], kb);
                        mma16(sf[mt][2 * p + 1], qf[mt][ks], kb + 2);
                    }
                }
            }

            // ---- deferred PV for tile kt-1 (stage (st+3)&3) ----
            if (kt > 0) {
                #pragma unroll
                for (int mt = 0; mt < 2; mt++)
                    #pragma unroll
                    for (int nt = 0; nt < 8; nt++) {
                        acc[mt][nt][0] *= al0s[mt]; acc[mt][nt][1] *= al0s[mt];
                        acc[mt][nt][2] *= al1s[mt]; acc[mt][nt][3] *= al1s[mt];
                    }
                int pv_st = (st + 3) & 3;
                #pragma unroll
                for (int ks = 0; ks < 4; ks++) {
                    #pragma unroll
                    for (int p = 0; p < 4; p++) {
                        uint32_t vb[4];
                        ldm_x4t(vb, vfrag_base + (uint32_t)(pv_st * FKV_H * 2)
                                    + (uint32_t)((ks * 16 * FQSTR + p * 16) << 1));
                        #pragma unroll
                        for (int mt = 0; mt < 2; mt++) {
                            uint32_t af[4];
                            af[0] = ph[mt][2 * ks][0];
                            af[1] = ph[mt][2 * ks][1];
                            af[2] = ph[mt][2 * ks + 1][0];
                            af[3] = ph[mt][2 * ks + 1][1];
                            mma16(acc[mt][2 * p],     af, vb);
                            mma16(acc[mt][2 * p + 1], af, vb + 2);
                        }
                    }
                }
            }

            // ---- softmax for tile kt (fills ph, al for next iteration) ----
            #pragma unroll
            for (int mt = 0; mt < 2; mt++) {
                float mx0 = -1e30f, mx1 = -1e30f;
                #pragma unroll
                for (int nt = 0; nt < 8; nt++) {
                    float bia0 = mk[nt * 8 + 2 * c]     ? 0.f : MBIAS;
                    float bia1 = mk[nt * 8 + 2 * c + 1] ? 0.f : MBIAS;
                    sf[mt][nt][0] += bia0; sf[mt][nt][1] += bia1;
                    sf[mt][nt][2] += bia0; sf[mt][nt][3] += bia1;
                    mx0 = fmaxf(mx0, fmaxf(sf[mt][nt][0], sf[mt][nt][1]));
                    mx1 = fmaxf(mx1, fmaxf(sf[mt][nt][2], sf[mt][nt][3]));
                }
                mx0 = fmaxf(mx0, __shfl_xor_sync(0xffffffffu, mx0, 1));
                mx0 = fmaxf(mx0, __shfl_xor_sync(0xffffffffu, mx0, 2));
                mx1 = fmaxf(mx1, __shfl_xor_sync(0xffffffffu, mx1, 1));
                mx1 = fmaxf(mx1, __shfl_xor_sync(0xffffffffu, mx1, 2));

                float mn0 = fmaxf(m0[mt], mx0), mn1 = fmaxf(m1[mt], mx1);
                float al0 = ex2f(m0[mt] - mn0), al1 = ex2f(m1[mt] - mn1);
                m0[mt] = mn0; m1[mt] = mn1;
                al0s[mt] = al0; al1s[mt] = al1;

                __half2 hs0 = __float2half2_rn(0.f), hs1 = hs0;
                #pragma unroll
                for (int nt = 0; nt < 8; nt++) {
                    uint32_t e0 = h2exp2_u(sf[mt][nt][0] - mn0, sf[mt][nt][1] - mn0);
                    uint32_t e1 = h2exp2_u(sf[mt][nt][2] - mn1, sf[mt][nt][3] - mn1);
                    ph[mt][nt][0] = e0;
                    ph[mt][nt][1] = e1;
                    hs0 = __hadd2(hs0, *(__half2*)&e0);
                    hs1 = __hadd2(hs1, *(__half2*)&e1);
                }
                float ps0 = __low2float(hs0) + __high2float(hs0);
                float ps1 = __low2float(hs1) + __high2float(hs1);
                ps0 += __shfl_xor_sync(0xffffffffu, ps0, 1);
                ps0 += __shfl_xor_sync(0xffffffffu, ps0, 2);
                ps1 += __shfl_xor_sync(0xffffffffu, ps1, 1);
                ps1 += __shfl_xor_sync(0xffffffffu, ps1, 2);
                l0[mt] = l0[mt] * al0 + ps0;
                l1[mt] = l1[mt] * al1 + ps1;
            }
        }
    }

    // ---- final deferred PV for the last tile (stage (NT_KV-1)&3) ----
    {
        #pragma unroll
        for (int mt = 0; mt < 2; mt++)
            #pragma unroll
            for (int nt = 0; nt < 8; nt++) {
                acc[mt][nt][0] *= al0s[mt]; acc[mt][nt][1] *= al0s[mt];
                acc[mt][nt][2] *= al1s[mt]; acc[mt][nt][3] *= al1s[mt];
            }
        const int pv_st = (NT_KV - 1) & 3;
        #pragma unroll
        for (int ks = 0; ks < 4; ks++) {
            #pragma unroll
            for (int p = 0; p < 4; p++) {
                uint32_t vb[4];
                ldm_x4t(vb, vfrag_base + (uint32_t)(pv_st * FKV_H * 2)
                            + (uint32_t)((ks * 16 * FQSTR + p * 16) << 1));
                #pragma unroll
                for (int mt = 0; mt < 2; mt++) {
                    uint32_t af[4];
                    af[0] = ph[mt][2 * ks][0];
                    af[1] = ph[mt][2 * ks][1];
                    af[2] = ph[mt][2 * ks + 1][0];
                    af[3] = ph[mt][2 * ks + 1][1];
                    mma16(acc[mt][2 * p],     af, vb);
                    mma16(acc[mt][2 * p + 1], af, vb + 2);
                }
            }
        }
    }

    #pragma unroll
    for (int mt = 0; mt < 2; mt++) {
        float inv0 = 1.f / l0[mt], inv1 = 1.f / l1[mt];
        size_t r0 = ((size_t)(b * SS + q0 + qb + mt * 16 + g)) * DD + h * DHD;
        size_t r1 = r0 + 8 * DD;
        #pragma unroll
        for (int nt = 0; nt < 8; nt++) {
            int col = nt * 8 + 2 * c;
            *(__half2*)(O + r0 + col) =
                __floats2half2_rn(acc[mt][nt][0] * inv0, acc[mt][nt][1] * inv0);
            *(__half2*)(O + r1 + col) =
                __floats2half2_rn(acc[mt][nt][2] * inv1, acc[mt][nt][3] * inv1);
        }
    }
}

// ---------------- launch ---------------------------------------------------
extern "C" void kernel_launch(void* const* d_in, const int* in_sizes, int n_in,
                              void* d_out, int out_size)
{
    const float* hidden = (const float*)d_in[0];
    const int*   mask   = (const int*)d_in[1];
    const float* wq = (const float*)d_in[2];
    const float* bq = (const float*)d_in[3];
    const float* wk = (const float*)d_in[4];
    const float* bk = (const float*)d_in[5];
    const float* wv = (const float*)d_in[6];
    const float* bv = (const float*)d_in[7];
    const float* wo = (const float*)d_in[8];
    const float* bo = (const float*)d_in[9];
    const float* w1 = (const float*)d_in[10];
    const float* b1 = (const float*)d_in[11];
    const float* w2 = (const float*)d_in[12];
    const float* b2 = (const float*)d_in[13];
    const float* ln1_g = (const float*)d_in[14];
    const float* ln1_b = (const float*)d_in[15];
    const float* ln2_g = (const float*)d_in[16];
    const float* ln2_b = (const float*)d_in[17];
    float* out = (float*)d_out;

    __half *ln, *qkv, *attn, *f1, *wqkvh, *woh, *w1h, *w2h;
    float *h1, *bqkv;
    cudaGetSymbolAddress((void**)&ln,    g_ln);
    cudaGetSymbolAddress((void**)&qkv,   g_qkv);
    cudaGetSymbolAddress((void**)&attn,  g_attn);
    cudaGetSymbolAddress((void**)&h1,    g_h1);
    cudaGetSymbolAddress((void**)&f1,    g_f1);
    cudaGetSymbolAddress((void**)&wqkvh, g_wqkv);
    cudaGetSymbolAddress((void**)&bqkv,  g_bqkv);
    cudaGetSymbolAddress((void**)&woh,   g_wo);
    cudaGetSymbolAddress((void**)&w1h,   g_w1);
    cudaGetSymbolAddress((void**)&w2h,   g_w2);

    cudaFuncSetAttribute(flash_f16,
                         cudaFuncAttributeMaxDynamicSharedMemorySize, FLASH_SMEM);
    cudaFuncSetAttribute(gemm_f16<1>,
                         cudaFuncAttributeMaxDynamicSharedMemorySize, GEMM_SMEM);
    cudaFuncSetAttribute(gemm_f16<2>,
                         cudaFuncAttributeMaxDynamicSharedMemorySize, GEMM_SMEM);
    cudaFuncSetAttribute(gemm_f16<3>,
                         cudaFuncAttributeMaxDynamicSharedMemorySize, GEMM_SMEM);

    // one fused pack launch
    pack_all<<<(unsigned)PACK_BLOCKS, 256>>>(wq, wk, wv, wo, w1, w2, bq, bk, bv,
                                             wqkvh, woh, w1h, w2h, bqkv);

    // 1) LN1 (warp-per-row)
    ln_kernel<<<NROWS / 8, 256>>>(hidden, ln1_g, ln1_b, ln);

    // 2) fused QKV projection -> fp16
    dim3 gQKV(NQKV / 128, NROWS / 128);
    gemm_f16<3><<<gQKV, 128, GEMM_SMEM>>>(ln, wqkvh, bqkv, nullptr, qkv,
                                          NROWS, DD, NQKV);

    // 3) attention
    flash_f16<<<dim3(SS / 128, HH, BB), 128, FLASH_SMEM>>>(
        qkv, qkv + DD, qkv + 2 * DD, NQKV, mask, attn);

    // 4) output projection + residual -> fp32
    dim3 gD(DD / 128, NROWS / 128);
    gemm_f16<2><<<gD, 128, GEMM_SMEM>>>(attn, woh, bo, hidden, h1, NROWS, DD, DD);

    // 5) LN2
    ln_kernel<<<NROWS / 8, 256>>>(h1, ln2_g, ln2_b, ln);

    // 6) FFN
    dim3 gF(DFF / 128, NROWS / 128);
    gemm_f16<1><<<gF, 128, GEMM_SMEM>>>(ln, w1h, b1, nullptr, f1, NROWS, DD, DFF);
    gemm_f16<2><<<gD, 128, GEMM_SMEM>>>(f1, w2h, b2, h1, out, NROWS, DFF, DD);
}

// round 16
// speedup vs baseline: 1.3001x; 1.1205x over previous
#include <cuda_runtime.h>
#include <cuda_fp16.h>
#include <math.h>
#include <stdint.h>

#define BB 2
#define SS 2048
#define DD 1024
#define HH 16
#define DHD 64
#define DFF 4096
#define NROWS (BB * SS)
#define NQKV 3072

// ---------------- scratch (device globals; no allocation) ----------------
__device__ __half g_ln[NROWS * DD];
__device__ __half g_qkv[NROWS * NQKV];
__device__ __half g_attn[NROWS * DD];
__device__ float  g_h1[NROWS * DD];
__device__ __half g_f1[NROWS * DFF];
__device__ __half g_wqkv[DD * NQKV];
__device__ float  g_bqkv[NQKV];
__device__ __half g_wo[DD * DD];
__device__ __half g_w1[DD * DFF];
__device__ __half g_w2[DFF * DD];

// ---------------- helpers --------------------------------------------------
__device__ __forceinline__ uint32_t smem_u32(const void* p) {
    uint32_t a;
    asm("{ .reg .u64 t; cvta.to.shared.u64 t, %1; cvt.u32.u64 %0, t; }" : "=r"(a) : "l"(p));
    return a;
}
__device__ __forceinline__ void cp16(void* dst_smem, const void* src) {
    uint32_t d;
    asm("{ .reg .u64 t; cvta.to.shared.u64 t, %1; cvt.u32.u64 %0, t; }"
        : "=r"(d) : "l"(dst_smem));
    asm volatile("cp.async.cg.shared.global [%0], [%1], 16;" :: "r"(d), "l"(src));
}
__device__ __forceinline__ void cp_commit() {
    asm volatile("cp.async.commit_group;");
}
template <int N>
__device__ __forceinline__ void cp_wait() {
    asm volatile("cp.async.wait_group %0;" :: "n"(N));
}
__device__ __forceinline__ void ldm_x4(uint32_t r[4], uint32_t addr) {
    asm volatile("ldmatrix.sync.aligned.m8n8.x4.shared.b16 {%0,%1,%2,%3}, [%4];"
        : "=r"(r[0]), "=r"(r[1]), "=r"(r[2]), "=r"(r[3]) : "r"(addr));
}
__device__ __forceinline__ void ldm_x4t(uint32_t r[4], uint32_t addr) {
    asm volatile("ldmatrix.sync.aligned.m8n8.x4.trans.shared.b16 {%0,%1,%2,%3}, [%4];"
        : "=r"(r[0]), "=r"(r[1]), "=r"(r[2]), "=r"(r[3]) : "r"(addr));
}
__device__ __forceinline__ void mma16(float c[4], const uint32_t a[4], const uint32_t b[2]) {
    asm volatile(
        "mma.sync.aligned.m16n8k16.row.col.f32.f16.f16.f32 "
        "{%0,%1,%2,%3}, {%4,%5,%6,%7}, {%8,%9}, {%0,%1,%2,%3};"
        : "+f"(c[0]), "+f"(c[1]), "+f"(c[2]), "+f"(c[3])
        : "r"(a[0]), "r"(a[1]), "r"(a[2]), "r"(a[3]), "r"(b[0]), "r"(b[1]));
}
__device__ __forceinline__ float ex2f(float x) {
    float r;
    asm("ex2.approx.f32 %0, %1;" : "=f"(r) : "f"(x));
    return r;
}
__device__ __forceinline__ uint32_t h2exp2_u(float a, float b) {
    __half2 h = __floats2half2_rn(a, b);
    uint32_t x = *(uint32_t*)&h, r;
    asm("ex2.approx.f16x2 %0, %1;" : "=r"(r) : "r"(x));
    return r;
}
__device__ __forceinline__ float gelu_tanh_f(float h) {
    const float c = 0.7978845608028654f;
    float u = c * (h + 0.044715f * h * h * h);
    return 0.5f * h * (1.0f + tanhf(u));
}

// ---------------- ONE fused pack kernel, 8 float4 in flight per thread -----
#define NW (DD * DD / 4)
#define NF (DD * DFF / 4)
#define PACK_TOT (4L * NW + 2L * NF + 768)
#define PACK_BLOCKS ((PACK_TOT + 2047) / 2048)
__global__ void __launch_bounds__(256) pack_all(
    const float* __restrict__ wq, const float* __restrict__ wk,
    const float* __restrict__ wv, const float* __restrict__ wo,
    const float* __restrict__ w1, const float* __restrict__ w2,
    const float* __restrict__ bq, const float* __restrict__ bk,
    const float* __restrict__ bv,
    __half* __restrict__ wqkv, __half* __restrict__ woh,
    __half* __restrict__ w1h, __half* __restrict__ w2h,
    float* __restrict__ bqkv)
{
    #pragma unroll
    for (int j = 0; j < 8; j++) {
        long i = (long)blockIdx.x * 2048 + j * 256 + threadIdx.x;
        if (i >= PACK_TOT) break;
        if (i < 3L * NW) {
            const float* src = (i < NW) ? wq : (i < 2L * NW) ? wk : wv;
            int coff = (i < NW) ? 0 : (i < 2L * NW) ? DD : 2 * DD;
            long ii = i % NW;
            int row = (int)(ii >> 8), c4 = ((int)ii & 255) << 2;
            float4 v = ((const float4*)src)[ii];
            __half2* o = (__half2*)(wqkv + (size_t)row * NQKV + coff + c4);
            o[0] = __floats2half2_rn(v.x, v.y);
            o[1] = __floats2half2_rn(v.z, v.w);
        } else if (i < 4L * NW) {
            long ii = i - 3L * NW;
            float4 v = ((const float4*)wo)[ii];
            __half2* o = (__half2*)(woh + ii * 4);
            o[0] = __floats2half2_rn(v.x, v.y);
            o[1] = __floats2half2_rn(v.z, v.w);
        } else if (i < 4L * NW + NF) {
            long ii = i - 4L * NW;
            float4 v = ((const float4*)w1)[ii];
            __half2* o = (__half2*)(w1h + ii * 4);
            o[0] = __floats2half2_rn(v.x, v.y);
            o[1] = __floats2half2_rn(v.z, v.w);
        } else if (i < 4L * NW + 2L * NF) {
            long ii = i - 4L * NW - NF;
            float4 v = ((const float4*)w2)[ii];
            __half2* o = (__half2*)(w2h + ii * 4);
            o[0] = __floats2half2_rn(v.x, v.y);
            o[1] = __floats2half2_rn(v.z, v.w);
        } else {
            long ii = i - 4L * NW - 2L * NF;   // 0..767
            int jj = (int)ii * 4;
            const float* src = (jj < DD) ? bq : (jj < 2 * DD) ? bk : bv;
            *(float4*)(bqkv + jj) = *(const float4*)(src + (jj & (DD - 1)));
        }
    }
}

// ---------------- LayerNorm: one warp per row, shfl-only -------------------
__global__ void __launch_bounds__(256) ln_kernel(
    const float* __restrict__ x, const float* __restrict__ gw,
    const float* __restrict__ bw, __half* __restrict__ y)
{
    int warp = threadIdx.x >> 5, lane = threadIdx.x & 31;
    int row = blockIdx.x * 8 + warp;
    const float4* xr = (const float4*)(x + (size_t)row * DD);

    float4 v[8];
    float s = 0.f, ss = 0.f;
    #pragma unroll
    for (int i = 0; i < 8; i++) {
        v[i] = xr[lane + i * 32];
        s  += v[i].x + v[i].y + v[i].z + v[i].w;
        ss += v[i].x * v[i].x + v[i].y * v[i].y + v[i].z * v[i].z + v[i].w * v[i].w;
    }
    #pragma unroll
    for (int o = 16; o; o >>= 1) {
        s  += __shfl_xor_sync(0xffffffffu, s,  o);
        ss += __shfl_xor_sync(0xffffffffu, ss, o);
    }
    float mean = s * (1.0f / DD);
    float var  = (ss - s * s * (1.0f / DD)) * (1.0f / (DD - 1));
    var = fmaxf(var, 0.f);
    float rd = 1.0f / (sqrtf(var) + 1e-6f);

    __half2* yo = (__half2*)(y + (size_t)row * DD);
    #pragma unroll
    for (int i = 0; i < 8; i++) {
        float4 g4 = ((const float4*)gw)[lane + i * 32];
        float4 b4 = ((const float4*)bw)[lane + i * 32];
        yo[2 * (lane + i * 32)] =
            __floats2half2_rn(g4.x * (v[i].x - mean) * rd + b4.x,
                              g4.y * (v[i].y - mean) * rd + b4.y);
        yo[2 * (lane + i * 32) + 1] =
            __floats2half2_rn(g4.z * (v[i].z - mean) * rd + b4.z,
                              g4.w * (v[i].w - mean) * rd + b4.w);
    }
}

// ---------------- fp16 mma GEMM (128x128x32, 4 warps x 64x64, 2 CTA/SM) ----
// Half-tile software pipeline: each 8-ldmatrix group issues under a 32-mma
// burst that does not depend on it; wait/sync sits between mma bursts.
#define TKH 32
#define ASTRH 40
#define BSTRH 136
#define A_TILE_H (128 * ASTRH)
#define B_TILE_H (TKH * BSTRH)
#define STAGE_H (A_TILE_H + B_TILE_H)
#define NSTG 4
#define GEMM_SMEM (NSTG * STAGE_H * 2)

// EPI: 1 = bias+gelu -> fp16 out, 2 = bias+residual -> fp32 out,
//      3 = bias -> fp16 out
template <int EPI>
__global__ void __launch_bounds__(128, 2) gemm_f16(
    const __half* __restrict__ A, const __half* __restrict__ W,
    const float* __restrict__ bias, const float* __restrict__ R,
    void* __restrict__ Cv, int M, int K, int N)
{
    extern __shared__ __half smh[];
    uint32_t sbase = smem_u32(smh);
    int t = threadIdx.x;
    int m0 = blockIdx.y * 128, n0 = blockIdx.x * 128;
    int nkt = K >> 5;

    auto load_tile = [&](int stg, int kt) {
        __half* As = smh + stg * STAGE_H;
        __half* Bs = As + A_TILE_H;
        int k0 = kt * TKH;
        #pragma unroll
        for (int i = 0; i < 4; i++) {
            int id = t + i * 128;
            int row = id >> 2, c8 = (id & 3) << 3;
            cp16(As + row * ASTRH + c8, A + (size_t)(m0 + row) * K + k0 + c8);
        }
        #pragma unroll
        for (int i = 0; i < 4; i++) {
            int id = t + i * 128;
            int row = id >> 4, c8 = (id & 15) << 3;
            cp16(Bs + row * BSTRH + c8, W + (size_t)(k0 + row) * N + n0 + c8);
        }
    };

    float acc[4][8][4];
    #pragma unroll
    for (int mt = 0; mt < 4; mt++)
        #pragma unroll
        for (int nt = 0; nt < 8; nt++)
            #pragma unroll
            for (int i = 0; i < 4; i++) acc[mt][nt][i] = 0.f;

    int lane = t & 31, wid = t >> 5;
    int warpM = wid >> 1, warpN = wid & 1;
    int g = lane >> 2, c = lane & 3;
    int arow_l = lane & 15;
    int acol_l = (lane >> 4) << 3;
    int mat = lane >> 3, lr = lane & 7;
    int bko = ((mat & 1) << 3) + lr;
    int bno = (mat >> 1) << 3;

    uint32_t af[2][4][4], b4[2][4][4];

    auto ldm_half = [&](int buf, uint32_t base_u, int ks) {
        uint32_t Bs_u = base_u + A_TILE_H * 2;
        #pragma unroll
        for (int mt = 0; mt < 4; mt++)
            ldm_x4(af[buf][mt], base_u +
                ((uint32_t)((warpM * 64 + mt * 16 + arow_l) * ASTRH
                            + ks * 16 + acol_l) << 1));
        #pragma unroll
        for (int p = 0; p < 4; p++) {
            int bk = ks * 16 + bko;
            int bn = warpN * 64 + p * 16 + bno;
            ldm_x4t(b4[p < 2 ? buf : buf][p], Bs_u +
                ((uint32_t)(bk * BSTRH + bn) << 1));
        }
    };
    auto mma_burst = [&](int buf) {
        #pragma unroll
        for (int mt = 0; mt < 4; mt++)
            #pragma unroll
            for (int nt = 0; nt < 8; nt++)
                mma16(acc[mt][nt], af[buf][mt], &b4[buf][nt >> 1][(nt & 1) << 1]);
    };

    // prologue: NSTG-1 tiles in flight; stage 0 ready; preload ks0 frags
    #pragma unroll
    for (int s = 0; s < NSTG - 1; s++) { load_tile(s, s); cp_commit(); }
    cp_wait<NSTG - 2>();
    __syncthreads();
    ldm_half(0, sbase, 0);

    for (int kt = 0; kt < nkt; kt++) {
        uint32_t cur_u = sbase + (uint32_t)((kt & (NSTG - 1)) * STAGE_H) * 2;

        // half 1: load ks1 frags (cur tile) under the ks0 mma burst
        ldm_half(1, cur_u, 1);
        mma_burst(0);

        // pipeline maintenance between bursts
        int nx = kt + NSTG - 1;
        if (nx < nkt) load_tile(nx & (NSTG - 1), nx);
        cp_commit();
        cp_wait<NSTG - 2>();
        __syncthreads();

        // half 2: load next tile's ks0 frags under the ks1 mma burst
        if (kt + 1 < nkt) {
            uint32_t nxt_u = sbase +
                (uint32_t)(((kt + 1) & (NSTG - 1)) * STAGE_H) * 2;
            ldm_half(0, nxt_u, 0);
        }
        mma_burst(1);
    }

    int rbase = m0 + warpM * 64 + g;
    int cbase = n0 + warpN * 64 + 2 * c;

    #pragma unroll
    for (int nt = 0; nt < 8; nt++) {
        int col = cbase + nt * 8;
        float2 b2 = *(const float2*)(bias + col);
        #pragma unroll
        for (int mt = 0; mt < 4; mt++) {
            int r0 = rbase + mt * 16;
            float v0x = acc[mt][nt][0] + b2.x;
            float v0y = acc[mt][nt][1] + b2.y;
            float v1x = acc[mt][nt][2] + b2.x;
            float v1y = acc[mt][nt][3] + b2.y;
            if (EPI == 2) {
                float* C = (float*)Cv;
                float2 r0v = *(const float2*)(R + (size_t)r0 * N + col);
                float2 r1v = *(const float2*)(R + (size_t)(r0 + 8) * N + col);
                *(float2*)(C + (size_t)r0 * N + col) =
                    make_float2(v0x + r0v.x, v0y + r0v.y);
                *(float2*)(C + (size_t)(r0 + 8) * N + col) =
                    make_float2(v1x + r1v.x, v1y + r1v.y);
            } else {
                if (EPI == 1) {
                    v0x = gelu_tanh_f(v0x); v0y = gelu_tanh_f(v0y);
                    v1x = gelu_tanh_f(v1x); v1y = gelu_tanh_f(v1y);
                }
                __half* C = (__half*)Cv;
                *(__half2*)(C + (size_t)r0 * N + col) = __floats2half2_rn(v0x, v0y);
                *(__half2*)(C + (size_t)(r0 + 8) * N + col) = __floats2half2_rn(v1x, v1y);
            }
        }
    }
}

// ---------------- fp16 flash attention (round-15 config, kept) --------------
#define FQSTR 72
#define FQ_H (128 * FQSTR)
#define FKV_H (64 * FQSTR)
#define KOFF FQ_H
#define VOFF (FQ_H + 4 * FKV_H)
#define MOFF_BYTES ((FQ_H + 8 * FKV_H) * 2)
#define FLASH_SMEM (MOFF_BYTES + 4 * 64 * 4 + 16)
#define QSCALE 0.1803368801111204f   /* 0.125 * log2(e) */
#define MBIAS  (-1.44269504e9f)      /* -1e9 * log2(e)  */
#define NT_KV (SS / 64)

__global__ void __launch_bounds__(128, 2) flash_f16(
    const __half* __restrict__ Q, const __half* __restrict__ Kg,
    const __half* __restrict__ Vg, int ldq, const int* __restrict__ mask,
    __half* __restrict__ O)
{
    extern __shared__ __half smh[];
    uint32_t sbase = smem_u32(smh);
    int* mksm = (int*)((char*)smh + MOFF_BYTES);
    int t = threadIdx.x;
    int lane = t & 31, wid = t >> 5;
    int g = lane >> 2, c = lane & 3;
    int q0 = blockIdx.x * 128;
    int h = blockIdx.y, b = blockIdx.z;
    size_t baseQ = ((size_t)(b * SS + q0)) * ldq + h * DHD;

    auto load_kv = [&](int kt, int s) {
        size_t baseK = ((size_t)(b * SS + kt * 64)) * ldq + h * DHD;
        __half* Kb = smh + KOFF + s * FKV_H;
        __half* Vb = smh + VOFF + s * FKV_H;
        #pragma unroll
        for (int i = 0; i < 4; i++) {
            int id = t + i * 128;
            int row = id >> 3, c8 = (id & 7) << 3;
            cp16(Kb + row * FQSTR + c8, Kg + baseK + (size_t)row * ldq + c8);
            cp16(Vb + row * FQSTR + c8, Vg + baseK + (size_t)row * ldq + c8);
        }
        if (t < 16) cp16(mksm + s * 64 + t * 4, mask + b * SS + kt * 64 + t * 4);
    };

    load_kv(0, 0);
    #pragma unroll
    for (int i = 0; i < 8; i++) {
        int id = t + i * 128;
        int row = id >> 3, c8 = (id & 7) << 3;
        cp16(smh + row * FQSTR + c8, Q + baseQ + (size_t)row * ldq + c8);
    }
    cp_commit();
    load_kv(1, 1);
    cp_commit();

    cp_wait<1>();
    __syncthreads();

    int arow_l = lane & 15;
    int acol_l = (lane >> 4) << 3;
    int mat = lane >> 3, lr = lane & 7;
    uint32_t qf[2][4][4];
    int qb = wid * 32;
    {
        __half2 qs = __float2half2_rn(QSCALE);
        #pragma unroll
        for (int mt = 0; mt < 2; mt++)
            #pragma unroll
            for (int ks = 0; ks < 4; ks++) {
                ldm_x4(qf[mt][ks], sbase +
                    ((uint32_t)((qb + mt * 16 + arow_l) * FQSTR
                                + ks * 16 + acol_l) << 1));
                #pragma unroll
                for (int i = 0; i < 4; i++) {
                    __half2 hv = *(__half2*)&qf[mt][ks][i];
                    hv = __hmul2(hv, qs);
                    qf[mt][ks][i] = *(uint32_t*)&hv;
                }
            }
    }

    float m0[2], m1[2], l0[2], l1[2];
    float al0s[2], al1s[2];
    #pragma unroll
    for (int mt = 0; mt < 2; mt++) {
        m0[mt] = -1e30f; m1[mt] = -1e30f; l0[mt] = 0.f; l1[mt] = 0.f;
        al0s[mt] = 1.f; al1s[mt] = 1.f;
    }
    float acc[2][8][4];
    #pragma unroll
    for (int mt = 0; mt < 2; mt++)
        #pragma unroll
        for (int nt = 0; nt < 8; nt++)
            #pragma unroll
            for (int i = 0; i < 4; i++) acc[mt][nt][i] = 0.f;

    uint32_t ph[2][8][2];

    uint32_t kfrag_base = sbase + ((uint32_t)(((mat >> 1) << 3) + lr) * FQSTR
                                   + ((mat & 1) << 3)) * 2 + KOFF * 2;
    uint32_t vfrag_base = sbase + ((uint32_t)((((mat & 1) << 3) + lr) * FQSTR)
                                   + (((mat >> 1) << 3))) * 2 + VOFF * 2;

    for (int kto = 0; kto < NT_KV; kto += 4) {
        #pragma unroll
        for (int st = 0; st < 4; st++) {
            int kt = kto + st;
            cp_wait<1>();
            __syncthreads();

            int nx = kt + 2;
            if (nx < NT_KV) load_kv(nx, nx & 3);
            cp_commit();

            const int* mk = mksm + st * 64;

            float sf[2][8][4];
            #pragma unroll
            for (int mt = 0; mt < 2; mt++)
                #pragma unroll
                for (int nt = 0; nt < 8; nt++)
                    #pragma unroll
                    for (int i = 0; i < 4; i++) sf[mt][nt][i] = 0.f;

            #pragma unroll
            for (int ks = 0; ks < 4; ks++) {
                #pragma unroll
                for (int p = 0; p < 4; p++) {
                    uint32_t kb[4];
                    ldm_x4(kb, kfrag_base + (uint32_t)(st * FKV_H * 2)
                               + (uint32_t)((p * 16 * FQSTR + ks * 16) << 1));
                    #pragma unroll
                    for (int mt = 0; mt < 2; mt++) {
                        mma16(sf[mt][2 * p],     qf[mt][ks], kb);
                        mma16(sf[mt][2 * p + 1], qf[mt][ks], kb + 2);
                    }
                }
            }

            if (kt > 0) {
                #pragma unroll
                for (int mt = 0; mt < 2; mt++)
                    #pragma unroll
                    for (int nt = 0; nt < 8; nt++) {
                        acc[mt][nt][0] *= al0s[mt]; acc[mt][nt][1] *= al0s[mt];
                        acc[mt][nt][2] *= al1s[mt]; acc[mt][nt][3] *= al1s[mt];
                    }
                int pv_st = (st + 3) & 3;
                #pragma unroll
                for (int ks = 0; ks < 4; ks++) {
                    #pragma unroll
                    for (int p = 0; p < 4; p++) {
                        uint32_t vb[4];
                        ldm_x4t(vb, vfrag_base + (uint32_t)(pv_st * FKV_H * 2)
                                    + (uint32_t)((ks * 16 * FQSTR + p * 16) << 1));
                        #pragma unroll
                        for (int mt = 0; mt < 2; mt++) {
                            uint32_t af[4];
                            af[0] = ph[mt][2 * ks][0];
                            af[1] = ph[mt][2 * ks][1];
                            af[2] = ph[mt][2 * ks + 1][0];
                            af[3] = ph[mt][2 * ks + 1][1];
                            mma16(acc[mt][2 * p],     af, vb);
                            mma16(acc[mt][2 * p + 1], af, vb + 2);
                        }
                    }
                }
            }

            #pragma unroll
            for (int mt = 0; mt < 2; mt++) {
                float mx0 = -1e30f, mx1 = -1e30f;
                #pragma unroll
                for (int nt = 0; nt < 8; nt++) {
                    float bia0 = mk[nt * 8 + 2 * c]     ? 0.f : MBIAS;
                    float bia1 = mk[nt * 8 + 2 * c + 1] ? 0.f : MBIAS;
                    sf[mt][nt][0] += bia0; sf[mt][nt][1] += bia1;
                    sf[mt][nt][2] += bia0; sf[mt][nt][3] += bia1;
                    mx0 = fmaxf(mx0, fmaxf(sf[mt][nt][0], sf[mt][nt][1]));
                    mx1 = fmaxf(mx1, fmaxf(sf[mt][nt][2], sf[mt][nt][3]));
                }
                mx0 = fmaxf(mx0, __shfl_xor_sync(0xffffffffu, mx0, 1));
                mx0 = fmaxf(mx0, __shfl_xor_sync(0xffffffffu, mx0, 2));
                mx1 = fmaxf(mx1, __shfl_xor_sync(0xffffffffu, mx1, 1));
                mx1 = fmaxf(mx1, __shfl_xor_sync(0xffffffffu, mx1, 2));

                float mn0 = fmaxf(m0[mt], mx0), mn1 = fmaxf(m1[mt], mx1);
                float al0 = ex2f(m0[mt] - mn0), al1 = ex2f(m1[mt] - mn1);
                m0[mt] = mn0; m1[mt] = mn1;
                al0s[mt] = al0; al1s[mt] = al1;

                __half2 hs0 = __float2half2_rn(0.f), hs1 = hs0;
                #pragma unroll
                for (int nt = 0; nt < 8; nt++) {
                    uint32_t e0 = h2exp2_u(sf[mt][nt][0] - mn0, sf[mt][nt][1] - mn0);
                    uint32_t e1 = h2exp2_u(sf[mt][nt][2] - mn1, sf[mt][nt][3] - mn1);
                    ph[mt][nt][0] = e0;
                    ph[mt][nt][1] = e1;
                    hs0 = __hadd2(hs0, *(__half2*)&e0);
                    hs1 = __hadd2(hs1, *(__half2*)&e1);
                }
                float ps0 = __low2float(hs0) + __high2float(hs0);
                float ps1 = __low2float(hs1) + __high2float(hs1);
                ps0 += __shfl_xor_sync(0xffffffffu, ps0, 1);
                ps0 += __shfl_xor_sync(0xffffffffu, ps0, 2);
                ps1 += __shfl_xor_sync(0xffffffffu, ps1, 1);
                ps1 += __shfl_xor_sync(0xffffffffu, ps1, 2);
                l0[mt] = l0[mt] * al0 + ps0;
                l1[mt] = l1[mt] * al1 + ps1;
            }
        }
    }

    {
        #pragma unroll
        for (int mt = 0; mt < 2; mt++)
            #pragma unroll
            for (int nt = 0; nt < 8; nt++) {
                acc[mt][nt][0] *= al0s[mt]; acc[mt][nt][1] *= al0s[mt];
                acc[mt][nt][2] *= al1s[mt]; acc[mt][nt][3] *= al1s[mt];
            }
        const int pv_st = (NT_KV - 1) & 3;
        #pragma unroll
        for (int ks = 0; ks < 4; ks++) {
            #pragma unroll
            for (int p = 0; p < 4; p++) {
                uint32_t vb[4];
                ldm_x4t(vb, vfrag_base + (uint32_t)(pv_st * FKV_H * 2)
                            + (uint32_t)((ks * 16 * FQSTR + p * 16) << 1));
                #pragma unroll
                for (int mt = 0; mt < 2; mt++) {
                    uint32_t af[4];
                    af[0] = ph[mt][2 * ks][0];
                    af[1] = ph[mt][2 * ks][1];
                    af[2] = ph[mt][2 * ks + 1][0];
                    af[3] = ph[mt][2 * ks + 1][1];
                    mma16(acc[mt][2 * p],     af, vb);
                    mma16(acc[mt][2 * p + 1], af, vb + 2);
                }
            }
        }
    }

    #pragma unroll
    for (int mt = 0; mt < 2; mt++) {
        float inv0 = 1.f / l0[mt], inv1 = 1.f / l1[mt];
        size_t r0 = ((size_t)(b * SS + q0 + qb + mt * 16 + g)) * DD + h * DHD;
        size_t r1 = r0 + 8 * DD;
        #pragma unroll
        for (int nt = 0; nt < 8; nt++) {
            int col = nt * 8 + 2 * c;
            *(__half2*)(O + r0 + col) =
                __floats2half2_rn(acc[mt][nt][0] * inv0, acc[mt][nt][1] * inv0);
            *(__half2*)(O + r1 + col) =
                __floats2half2_rn(acc[mt][nt][2] * inv1, acc[mt][nt][3] * inv1);
        }
    }
}

// ---------------- launch ---------------------------------------------------
extern "C" void kernel_launch(void* const* d_in, const int* in_sizes, int n_in,
                              void* d_out, int out_size)
{
    const float* hidden = (const float*)d_in[0];
    const int*   mask   = (const int*)d_in[1];
    const float* wq = (const float*)d_in[2];
    const float* bq = (const float*)d_in[3];
    const float* wk = (const float*)d_in[4];
    const float* bk = (const float*)d_in[5];
    const float* wv = (const float*)d_in[6];
    const float* bv = (const float*)d_in[7];
    const float* wo = (const float*)d_in[8];
    const float* bo = (const float*)d_in[9];
    const float* w1 = (const float*)d_in[10];
    const float* b1 = (const float*)d_in[11];
    const float* w2 = (const float*)d_in[12];
    const float* b2 = (const float*)d_in[13];
    const float* ln1_g = (const float*)d_in[14];
    const float* ln1_b = (const float*)d_in[15];
    const float* ln2_g = (const float*)d_in[16];
    const float* ln2_b = (const float*)d_in[17];
    float* out = (float*)d_out;

    __half *ln, *qkv, *attn, *f1, *wqkvh, *woh, *w1h, *w2h;
    float *h1, *bqkv;
    cudaGetSymbolAddress((void**)&ln,    g_ln);
    cudaGetSymbolAddress((void**)&qkv,   g_qkv);
    cudaGetSymbolAddress((void**)&attn,  g_attn);
    cudaGetSymbolAddress((void**)&h1,    g_h1);
    cudaGetSymbolAddress((void**)&f1,    g_f1);
    cudaGetSymbolAddress((void**)&wqkvh, g_wqkv);
    cudaGetSymbolAddress((void**)&bqkv,  g_bqkv);
    cudaGetSymbolAddress((void**)&woh,   g_wo);
    cudaGetSymbolAddress((void**)&w1h,   g_w1);
    cudaGetSymbolAddress((void**)&w2h,   g_w2);

    cudaFuncSetAttribute(flash_f16,
                         cudaFuncAttributeMaxDynamicSharedMemorySize, FLASH_SMEM);
    cudaFuncSetAttribute(gemm_f16<1>,
                         cudaFuncAttributeMaxDynamicSharedMemorySize, GEMM_SMEM);
    cudaFuncSetAttribute(gemm_f16<2>,
                         cudaFuncAttributeMaxDynamicSharedMemorySize, GEMM_SMEM);
    cudaFuncSetAttribute(gemm_f16<3>,
                         cudaFuncAttributeMaxDynamicSharedMemorySize, GEMM_SMEM);

    // one fused pack launch
    pack_all<<<(unsigned)PACK_BLOCKS, 256>>>(wq, wk, wv, wo, w1, w2, bq, bk, bv,
                                             wqkvh, woh, w1h, w2h, bqkv);

    // 1) LN1 (warp-per-row)
    ln_kernel<<<NROWS / 8, 256>>>(hidden, ln1_g, ln1_b, ln);

    // 2) fused QKV projection -> fp16
    dim3 gQKV(NQKV / 128, NROWS / 128);
    gemm_f16<3><<<gQKV, 128, GEMM_SMEM>>>(ln, wqkvh, bqkv, nullptr, qkv,
                                          NROWS, DD, NQKV);

    // 3) attention
    flash_f16<<<dim3(SS / 128, HH, BB), 128, FLASH_SMEM>>>(
        qkv, qkv + DD, qkv + 2 * DD, NQKV, mask, attn);

    // 4) output projection + residual -> fp32
    dim3 gD(DD / 128, NROWS / 128);
    gemm_f16<2><<<gD, 128, GEMM_SMEM>>>(attn, woh, bo, hidden, h1, NROWS, DD, DD);

    // 5) LN2
    ln_kernel<<<NROWS / 8, 256>>>(h1, ln2_g, ln2_b, ln);

    // 6) FFN
    dim3 gF(DFF / 128, NROWS / 128);
    gemm_f16<1><<<gF, 128, GEMM_SMEM>>>(ln, w1h, b1, nullptr, f1, NROWS, DD, DFF);
    gemm_f16<2><<<gD, 128, GEMM_SMEM>>>(f1, w2h, b2, h1, out, NROWS, DFF, DD);
}